// round 1
// baseline (speedup 1.0000x reference)
#include <cuda_runtime.h>
#include <math.h>

#define N_NODES 50000
#define E_EDGES 800000
#define D_DIM   128
#define A_DIM   5

// Scratch (no allocations allowed in kernel_launch)
__device__ float g_node_px[N_NODES * D_DIM];   // node_px [N,128]
__device__ float g_s[N_NODES * 10];            // per node: s_src[5] | s_dst[5]
__device__ float g_bsum[N_NODES * A_DIM];      // scattered sum of b vectors

// ---------------------------------------------------------------------------
// Kernel 1: per-node precompute.
//  - attention softmax + node_px = x + w @ anchor_node
//  - s_src = x @ w_w[0:128,:], s_dst = x @ w_w[128:256,:]
//  - zero g_bsum
// One warp per node.
// ---------------------------------------------------------------------------
__global__ void node_pre_kernel(const float* __restrict__ x,
                                const float* __restrict__ anchor_node,
                                const float* __restrict__ attn_w,
                                const float* __restrict__ attn_b,
                                const float* __restrict__ w_w)
{
    __shared__ float sh_attn[D_DIM * A_DIM];       // [d][a]
    __shared__ float sh_ww[2 * D_DIM * A_DIM];     // [d][a]
    __shared__ float sh_an[A_DIM * D_DIM];         // [a][d]
    __shared__ float sh_ab[A_DIM];

    int tid = threadIdx.x;
    for (int i = tid; i < D_DIM * A_DIM; i += blockDim.x) sh_attn[i] = attn_w[i];
    for (int i = tid; i < 2 * D_DIM * A_DIM; i += blockDim.x) sh_ww[i] = w_w[i];
    for (int i = tid; i < A_DIM * D_DIM; i += blockDim.x) sh_an[i] = anchor_node[i];
    if (tid < A_DIM) sh_ab[tid] = attn_b[tid];
    __syncthreads();

    int warp = blockIdx.x * (blockDim.x >> 5) + (tid >> 5);
    int lane = tid & 31;
    if (warp >= N_NODES) return;
    int n = warp;

    float4 xv = reinterpret_cast<const float4*>(x + (size_t)n * D_DIM)[lane];
    float xs[4] = {xv.x, xv.y, xv.z, xv.w};
    int p0 = lane * 4;

    float aA[A_DIM], aS[A_DIM], aD[A_DIM];
#pragma unroll
    for (int c = 0; c < A_DIM; c++) { aA[c] = 0.f; aS[c] = 0.f; aD[c] = 0.f; }

#pragma unroll
    for (int j = 0; j < 4; j++) {
        int p = p0 + j;
        float xj = xs[j];
#pragma unroll
        for (int c = 0; c < A_DIM; c++) {
            aA[c] = fmaf(xj, sh_attn[p * A_DIM + c], aA[c]);
            aS[c] = fmaf(xj, sh_ww[p * A_DIM + c], aS[c]);
            aD[c] = fmaf(xj, sh_ww[(D_DIM + p) * A_DIM + c], aD[c]);
        }
    }
#pragma unroll
    for (int off = 16; off > 0; off >>= 1) {
#pragma unroll
        for (int c = 0; c < A_DIM; c++) {
            aA[c] += __shfl_xor_sync(0xffffffffu, aA[c], off);
            aS[c] += __shfl_xor_sync(0xffffffffu, aS[c], off);
            aD[c] += __shfl_xor_sync(0xffffffffu, aD[c], off);
        }
    }

    // softmax(aA + attn_b) over 5
    float wgt[A_DIM];
    float m = -1e30f;
#pragma unroll
    for (int c = 0; c < A_DIM; c++) { wgt[c] = aA[c] + sh_ab[c]; m = fmaxf(m, wgt[c]); }
    float ssum = 0.f;
#pragma unroll
    for (int c = 0; c < A_DIM; c++) { wgt[c] = expf(wgt[c] - m); ssum += wgt[c]; }
    float inv = 1.0f / ssum;
#pragma unroll
    for (int c = 0; c < A_DIM; c++) wgt[c] *= inv;

    float ov[4];
#pragma unroll
    for (int j = 0; j < 4; j++) {
        int p = p0 + j;
        float v = xs[j];
#pragma unroll
        for (int c = 0; c < A_DIM; c++) v = fmaf(wgt[c], sh_an[c * D_DIM + p], v);
        ov[j] = v;
    }
    float4 o = {ov[0], ov[1], ov[2], ov[3]};
    reinterpret_cast<float4*>(g_node_px + (size_t)n * D_DIM)[lane] = o;

    if (lane == 0) {
#pragma unroll
        for (int c = 0; c < A_DIM; c++) {
            g_s[n * 10 + c]     = aS[c];
            g_s[n * 10 + 5 + c] = aD[c];
            g_bsum[n * A_DIM + c] = 0.f;
        }
    }
}

// ---------------------------------------------------------------------------
// Kernel 2: per-edge. logits via gathered 5-vectors; b = softmax(leaky_relu);
// write edge_prompt = b @ anchor_edge (512B coalesced); scatter b into g_bsum.
// One warp per edge (grid-stride).
// ---------------------------------------------------------------------------
__global__ void edge_kernel(const int* __restrict__ edge_index,
                            const float* __restrict__ anchor_edge,
                            const float* __restrict__ w_b,
                            float* __restrict__ out_edge)
{
    __shared__ float sh_ae[A_DIM * D_DIM];
    __shared__ float sh_wb[A_DIM];
    int tid = threadIdx.x;
    for (int i = tid; i < A_DIM * D_DIM; i += blockDim.x) sh_ae[i] = anchor_edge[i];
    if (tid < A_DIM) sh_wb[tid] = w_b[tid];
    __syncthreads();

    int lane = tid & 31;
    int warp0 = blockIdx.x * (blockDim.x >> 5) + (tid >> 5);
    int nwarps = gridDim.x * (blockDim.x >> 5);

    for (int e = warp0; e < E_EDGES; e += nwarps) {
        int src = edge_index[e];
        int dst = edge_index[E_EDGES + e];

        float sval = 0.f;
        if (lane < 10) {
            int nidx = (lane < 5) ? src : dst;
            sval = g_s[nidx * 10 + lane];   // lanes 0-4: s_src(src); 5-9: s_dst(dst)
        }

        float b[A_DIM];
        float m = -1e30f;
#pragma unroll
        for (int c = 0; c < A_DIM; c++) {
            float l = __shfl_sync(0xffffffffu, sval, c)
                    + __shfl_sync(0xffffffffu, sval, 5 + c)
                    + sh_wb[c];
            l = (l > 0.f) ? l : 0.01f * l;     // leaky_relu, slope 0.01
            b[c] = l;
            m = fmaxf(m, l);
        }
        float ssum = 0.f;
#pragma unroll
        for (int c = 0; c < A_DIM; c++) { b[c] = expf(b[c] - m); ssum += b[c]; }
        float inv = 1.0f / ssum;
#pragma unroll
        for (int c = 0; c < A_DIM; c++) b[c] *= inv;

        int p0 = lane * 4;
        float ov[4];
#pragma unroll
        for (int j = 0; j < 4; j++) {
            float v = 0.f;
#pragma unroll
            for (int c = 0; c < A_DIM; c++) v = fmaf(b[c], sh_ae[c * D_DIM + p0 + j], v);
            ov[j] = v;
        }
        float4 o = {ov[0], ov[1], ov[2], ov[3]};
        reinterpret_cast<float4*>(out_edge + (size_t)e * D_DIM)[lane] = o;

        // scatter b into bsum (5 atomics per endpoint, spread across lanes)
#pragma unroll
        for (int c = 0; c < A_DIM; c++) {
            if (lane == c)      atomicAdd(&g_bsum[src * A_DIM + c], b[c]);
            if (lane == 16 + c) atomicAdd(&g_bsum[dst * A_DIM + c], b[c]);
        }
    }
}

// ---------------------------------------------------------------------------
// Kernel 3: fused node-side GEMMs.
//  agg = bsum @ anchor_edge
//  h   = relu([node_px, agg] @ cd1_w + cd1_b)
//  cs  = sigmoid(h @ cd2_w + cd2_b)
//  tv  = (node_px + agg) @ int_w + int_b
//  out = node_px + cs * tv
// 128 rows / block, 256 threads, 8x8 register tile per thread.
// ---------------------------------------------------------------------------
#define TM 128
#define SPITCH 132
#define SMEM_FLOATS (3 * TM * SPITCH + 32 * D_DIM)
#define SMEM_BYTES  (SMEM_FLOATS * 4)

__global__ __launch_bounds__(256, 1) void node_post_kernel(
    const float* __restrict__ anchor_edge,
    const float* __restrict__ cd1_w, const float* __restrict__ cd1_b,
    const float* __restrict__ cd2_w, const float* __restrict__ cd2_b,
    const float* __restrict__ int_w, const float* __restrict__ int_b,
    float* __restrict__ out_final)
{
    extern __shared__ float smem[];
    float* spx  = smem;                       // [128][SPITCH]
    float* sagg = spx  + TM * SPITCH;         // [128][SPITCH]
    float* sh2  = sagg + TM * SPITCH;         // [128][SPITCH]  h, then cs
    float* sW   = sh2  + TM * SPITCH;         // [32][128]

    int tid = threadIdx.x;
    int row0 = blockIdx.x * TM;

    // Stage node_px; build agg = bsum @ anchor_edge on the fly
    for (int idx = tid; idx < TM * D_DIM; idx += 256) {
        int r = idx >> 7, c = idx & 127;
        int n = row0 + r;
        float px = 0.f, ag = 0.f;
        if (n < N_NODES) {
            px = g_node_px[(size_t)n * D_DIM + c];
#pragma unroll
            for (int a = 0; a < A_DIM; a++)
                ag = fmaf(g_bsum[n * A_DIM + a], anchor_edge[a * D_DIM + c], ag);
        }
        spx[r * SPITCH + c]  = px;
        sagg[r * SPITCH + c] = ag;
    }
    __syncthreads();

    int tr = tid >> 4, tc = tid & 15;
    int rb = tr * 8, cb = tc * 8;
    float acc[8][8];

    // ---- GEMM1: [px|agg] @ cd1_w (K=256) ----
#pragma unroll
    for (int i = 0; i < 8; i++)
#pragma unroll
        for (int j = 0; j < 8; j++) acc[i][j] = 0.f;

    for (int kb = 0; kb < 256; kb += 32) {
        for (int idx = tid; idx < 32 * 128; idx += 256)
            sW[idx] = cd1_w[kb * 128 + idx];
        __syncthreads();
        const float* Ab = (kb < 128) ? spx : sagg;
        int kofs = kb & 127;
#pragma unroll
        for (int kk = 0; kk < 32; kk++) {
            float a[8], bb[8];
#pragma unroll
            for (int i = 0; i < 8; i++) a[i] = Ab[(rb + i) * SPITCH + kofs + kk];
#pragma unroll
            for (int j = 0; j < 8; j++) bb[j] = sW[kk * 128 + cb + j];
#pragma unroll
            for (int i = 0; i < 8; i++)
#pragma unroll
                for (int j = 0; j < 8; j++) acc[i][j] = fmaf(a[i], bb[j], acc[i][j]);
        }
        __syncthreads();
    }
    {
        float bb[8];
#pragma unroll
        for (int j = 0; j < 8; j++) bb[j] = cd1_b[cb + j];
#pragma unroll
        for (int i = 0; i < 8; i++)
#pragma unroll
            for (int j = 0; j < 8; j++)
                sh2[(rb + i) * SPITCH + cb + j] = fmaxf(acc[i][j] + bb[j], 0.f);
    }
    __syncthreads();

    // ---- GEMM2: h @ cd2_w (K=128) -> causal strength ----
#pragma unroll
    for (int i = 0; i < 8; i++)
#pragma unroll
        for (int j = 0; j < 8; j++) acc[i][j] = 0.f;

    for (int kb = 0; kb < 128; kb += 32) {
        for (int idx = tid; idx < 32 * 128; idx += 256)
            sW[idx] = cd2_w[kb * 128 + idx];
        __syncthreads();
#pragma unroll
        for (int kk = 0; kk < 32; kk++) {
            float a[8], bb[8];
#pragma unroll
            for (int i = 0; i < 8; i++) a[i] = sh2[(rb + i) * SPITCH + kb + kk];
#pragma unroll
            for (int j = 0; j < 8; j++) bb[j] = sW[kk * 128 + cb + j];
#pragma unroll
            for (int i = 0; i < 8; i++)
#pragma unroll
                for (int j = 0; j < 8; j++) acc[i][j] = fmaf(a[i], bb[j], acc[i][j]);
        }
        __syncthreads();   // all reads of sh2 (h) done after last iteration
    }
    {
        float bb[8];
#pragma unroll
        for (int j = 0; j < 8; j++) bb[j] = cd2_b[cb + j];
#pragma unroll
        for (int i = 0; i < 8; i++)
#pragma unroll
            for (int j = 0; j < 8; j++) {
                float v = acc[i][j] + bb[j];
                sh2[(rb + i) * SPITCH + cb + j] = 1.0f / (1.0f + expf(-v));  // cs
            }
    }
    __syncthreads();

    // ---- GEMM3: (px+agg) @ int_w (K=128) ----
#pragma unroll
    for (int i = 0; i < 8; i++)
#pragma unroll
        for (int j = 0; j < 8; j++) acc[i][j] = 0.f;

    for (int kb = 0; kb < 128; kb += 32) {
        for (int idx = tid; idx < 32 * 128; idx += 256)
            sW[idx] = int_w[kb * 128 + idx];
        __syncthreads();
#pragma unroll
        for (int kk = 0; kk < 32; kk++) {
            float a[8], bb[8];
#pragma unroll
            for (int i = 0; i < 8; i++)
                a[i] = spx[(rb + i) * SPITCH + kb + kk] + sagg[(rb + i) * SPITCH + kb + kk];
#pragma unroll
            for (int j = 0; j < 8; j++) bb[j] = sW[kk * 128 + cb + j];
#pragma unroll
            for (int i = 0; i < 8; i++)
#pragma unroll
                for (int j = 0; j < 8; j++) acc[i][j] = fmaf(a[i], bb[j], acc[i][j]);
        }
        __syncthreads();
    }

    // ---- final: out = px + cs * (tv + int_b) ----
    {
        float bb[8];
#pragma unroll
        for (int j = 0; j < 8; j++) bb[j] = int_b[cb + j];
#pragma unroll
        for (int i = 0; i < 8; i++) {
            int n = row0 + rb + i;
            if (n < N_NODES) {
#pragma unroll
                for (int j = 0; j < 8; j++) {
                    float tv = acc[i][j] + bb[j];
                    float px = spx[(rb + i) * SPITCH + cb + j];
                    float cs = sh2[(rb + i) * SPITCH + cb + j];
                    out_final[(size_t)n * D_DIM + cb + j] = fmaf(cs, tv, px);
                }
            }
        }
    }
}

// ---------------------------------------------------------------------------
extern "C" void kernel_launch(void* const* d_in, const int* in_sizes, int n_in,
                              void* d_out, int out_size)
{
    const float* x           = (const float*)d_in[0];
    const float* anchor_node = (const float*)d_in[1];
    const float* attn_w      = (const float*)d_in[2];
    const float* attn_b      = (const float*)d_in[3];
    const float* anchor_edge = (const float*)d_in[4];
    const float* w_w         = (const float*)d_in[5];
    const float* w_b         = (const float*)d_in[6];
    const float* cd1_w       = (const float*)d_in[7];
    const float* cd1_b       = (const float*)d_in[8];
    const float* cd2_w       = (const float*)d_in[9];
    const float* cd2_b       = (const float*)d_in[10];
    const float* int_w       = (const float*)d_in[11];
    const float* int_b       = (const float*)d_in[12];
    const int*   edge_index  = (const int*)d_in[13];
    float* outp = (float*)d_out;   // [0, N*D) = final_x, [N*D, N*D+E*D) = edge_prompt

    node_pre_kernel<<<(N_NODES + 7) / 8, 256>>>(x, anchor_node, attn_w, attn_b, w_w);
    edge_kernel<<<2048, 256>>>(edge_index, anchor_edge, w_b,
                               outp + (size_t)N_NODES * D_DIM);
    cudaFuncSetAttribute(node_post_kernel,
                         cudaFuncAttributeMaxDynamicSharedMemorySize, SMEM_BYTES);
    node_post_kernel<<<(N_NODES + TM - 1) / TM, 256, SMEM_BYTES>>>(
        anchor_edge, cd1_w, cd1_b, cd2_w, cd2_b, int_w, int_b, outp);
}

// round 2
// speedup vs baseline: 1.9481x; 1.9481x over previous
#include <cuda_runtime.h>
#include <math.h>
#include <stdint.h>

#define N_NODES 50000
#define E_EDGES 800000
#define D_DIM   128
#define A_DIM   5

// Scratch (no allocations allowed in kernel_launch)
__device__ float g_node_px[N_NODES * D_DIM];  // node_px [N,128]
__device__ float g_s[N_NODES * 16];           // per node: s_src[5] @0, s_dst[5] @8 (padded)
__device__ float g_bsum[N_NODES * A_DIM];     // scattered sum of b vectors

__device__ __forceinline__ uint32_t f2tf(float f) {
    uint32_t r; asm("cvt.rna.tf32.f32 %0, %1;" : "=r"(r) : "f"(f)); return r;
}

__device__ __forceinline__ void mma_tf32(float* d, const uint32_t* a, const uint32_t* b) {
    asm volatile("mma.sync.aligned.m16n8k8.row.col.f32.tf32.tf32.f32 "
        "{%0,%1,%2,%3}, {%4,%5,%6,%7}, {%8,%9}, {%0,%1,%2,%3};"
        : "+f"(d[0]), "+f"(d[1]), "+f"(d[2]), "+f"(d[3])
        : "r"(a[0]), "r"(a[1]), "r"(a[2]), "r"(a[3]), "r"(b[0]), "r"(b[1]));
}

// ---------------------------------------------------------------------------
// Kernel 1: per-node precompute (one warp per node).
//  node_px = x + softmax(x@attn_w + attn_b) @ anchor_node
//  s_src = x @ w_w[0:128,:], s_dst = x @ w_w[128:256,:]  -> g_s (padded 16)
//  zero g_bsum
// Weight tiles transposed to [A][D] in smem so per-thread reads are float4.
// ---------------------------------------------------------------------------
__global__ __launch_bounds__(256) void node_pre_kernel(
    const float* __restrict__ x,
    const float* __restrict__ anchor_node,
    const float* __restrict__ attn_w,
    const float* __restrict__ attn_b,
    const float* __restrict__ w_w)
{
    __shared__ float shT[20 * D_DIM];   // attnT | wsT | wdT | anchor  (each [5][128])
    __shared__ float sh_ab[8];

    int tid = threadIdx.x;
    for (int i = tid; i < 640; i += 256) {
        int a = i >> 7, d = i & 127;
        shT[a * 128 + d]        = attn_w[d * A_DIM + a];
        shT[640 + a * 128 + d]  = w_w[d * A_DIM + a];
        shT[1280 + a * 128 + d] = w_w[(128 + d) * A_DIM + a];
        shT[1920 + i]           = anchor_node[i];
    }
    if (tid < A_DIM) sh_ab[tid] = attn_b[tid];
    __syncthreads();

    int warp = blockIdx.x * 8 + (tid >> 5);
    int lane = tid & 31;
    if (warp >= N_NODES) return;
    int n = warp;
    int p0 = lane * 4;

    float4 xv = reinterpret_cast<const float4*>(x + (size_t)n * D_DIM)[lane];

    float aA[A_DIM], aS[A_DIM], aD[A_DIM];
#pragma unroll
    for (int c = 0; c < A_DIM; c++) {
        float4 wa = *reinterpret_cast<const float4*>(&shT[c * 128 + p0]);
        float4 ws = *reinterpret_cast<const float4*>(&shT[640 + c * 128 + p0]);
        float4 wd = *reinterpret_cast<const float4*>(&shT[1280 + c * 128 + p0]);
        aA[c] = fmaf(xv.x, wa.x, fmaf(xv.y, wa.y, fmaf(xv.z, wa.z, xv.w * wa.w)));
        aS[c] = fmaf(xv.x, ws.x, fmaf(xv.y, ws.y, fmaf(xv.z, ws.z, xv.w * ws.w)));
        aD[c] = fmaf(xv.x, wd.x, fmaf(xv.y, wd.y, fmaf(xv.z, wd.z, xv.w * wd.w)));
    }
#pragma unroll
    for (int off = 16; off > 0; off >>= 1) {
#pragma unroll
        for (int c = 0; c < A_DIM; c++) {
            aA[c] += __shfl_xor_sync(0xffffffffu, aA[c], off);
            aS[c] += __shfl_xor_sync(0xffffffffu, aS[c], off);
            aD[c] += __shfl_xor_sync(0xffffffffu, aD[c], off);
        }
    }

    float wgt[A_DIM];
    float m = -1e30f;
#pragma unroll
    for (int c = 0; c < A_DIM; c++) { wgt[c] = aA[c] + sh_ab[c]; m = fmaxf(m, wgt[c]); }
    float ssum = 0.f;
#pragma unroll
    for (int c = 0; c < A_DIM; c++) { wgt[c] = __expf(wgt[c] - m); ssum += wgt[c]; }
    float inv = 1.0f / ssum;
#pragma unroll
    for (int c = 0; c < A_DIM; c++) wgt[c] *= inv;

    float4 o = xv;
#pragma unroll
    for (int c = 0; c < A_DIM; c++) {
        float4 an = *reinterpret_cast<const float4*>(&shT[1920 + c * 128 + p0]);
        o.x = fmaf(wgt[c], an.x, o.x);
        o.y = fmaf(wgt[c], an.y, o.y);
        o.z = fmaf(wgt[c], an.z, o.z);
        o.w = fmaf(wgt[c], an.w, o.w);
    }
    reinterpret_cast<float4*>(g_node_px + (size_t)n * D_DIM)[lane] = o;

    if (lane == 0) {
#pragma unroll
        for (int c = 0; c < A_DIM; c++) {
            g_s[n * 16 + c]     = aS[c];
            g_s[n * 16 + 8 + c] = aD[c];
            g_bsum[n * A_DIM + c] = 0.f;
        }
    }
}

// ---------------------------------------------------------------------------
// Kernel 2: edges. Phase A: one THREAD per edge computes b = softmax(
// leaky_relu(s_src[src]+s_dst[dst]+w_b)), scatters b (atomics), stages b in
// smem. Phase B: one WARP per edge writes edge_prompt = b @ anchor_edge
// (coalesced float4). 256 edges per block, E/256 = 3125 blocks exactly.
// ---------------------------------------------------------------------------
__global__ __launch_bounds__(256) void edge_kernel(
    const int* __restrict__ edge_index,
    const float* __restrict__ anchor_edge,
    const float* __restrict__ w_b,
    float* __restrict__ out_edge)
{
    __shared__ float sh_ae[A_DIM * D_DIM];
    __shared__ float sh_b[256 * A_DIM];
    __shared__ float sh_wb[8];

    int tid = threadIdx.x;
    for (int i = tid; i < A_DIM * D_DIM; i += 256) sh_ae[i] = anchor_edge[i];
    if (tid < A_DIM) sh_wb[tid] = w_b[tid];
    __syncthreads();

    int e0 = blockIdx.x * 256;
    int e = e0 + tid;
    {
        int src = edge_index[e];
        int dst = edge_index[E_EDGES + e];

        float4 s03 = *reinterpret_cast<const float4*>(&g_s[src * 16]);
        float  s4  = g_s[src * 16 + 4];
        float4 d03 = *reinterpret_cast<const float4*>(&g_s[dst * 16 + 8]);
        float  d4  = g_s[dst * 16 + 12];

        float b[A_DIM];
        b[0] = s03.x + d03.x + sh_wb[0];
        b[1] = s03.y + d03.y + sh_wb[1];
        b[2] = s03.z + d03.z + sh_wb[2];
        b[3] = s03.w + d03.w + sh_wb[3];
        b[4] = s4    + d4    + sh_wb[4];

        float m = -1e30f;
#pragma unroll
        for (int c = 0; c < A_DIM; c++) {
            b[c] = (b[c] > 0.f) ? b[c] : 0.01f * b[c];   // leaky_relu
            m = fmaxf(m, b[c]);
        }
        float ssum = 0.f;
#pragma unroll
        for (int c = 0; c < A_DIM; c++) { b[c] = __expf(b[c] - m); ssum += b[c]; }
        float inv = 1.0f / ssum;
#pragma unroll
        for (int c = 0; c < A_DIM; c++) {
            b[c] *= inv;
            sh_b[tid * A_DIM + c] = b[c];
            atomicAdd(&g_bsum[src * A_DIM + c], b[c]);
            atomicAdd(&g_bsum[dst * A_DIM + c], b[c]);
        }
    }
    __syncthreads();

    int lane = tid & 31, wid = tid >> 5;
    int p0 = lane * 4;
#pragma unroll 4
    for (int le = wid * 32; le < wid * 32 + 32; le++) {
        float b0 = sh_b[le * A_DIM + 0];
        float b1 = sh_b[le * A_DIM + 1];
        float b2 = sh_b[le * A_DIM + 2];
        float b3 = sh_b[le * A_DIM + 3];
        float b4 = sh_b[le * A_DIM + 4];
        float4 a0 = *reinterpret_cast<const float4*>(&sh_ae[0 * 128 + p0]);
        float4 a1 = *reinterpret_cast<const float4*>(&sh_ae[1 * 128 + p0]);
        float4 a2 = *reinterpret_cast<const float4*>(&sh_ae[2 * 128 + p0]);
        float4 a3 = *reinterpret_cast<const float4*>(&sh_ae[3 * 128 + p0]);
        float4 a4 = *reinterpret_cast<const float4*>(&sh_ae[4 * 128 + p0]);
        float4 o;
        o.x = fmaf(b0,a0.x, fmaf(b1,a1.x, fmaf(b2,a2.x, fmaf(b3,a3.x, b4*a4.x))));
        o.y = fmaf(b0,a0.y, fmaf(b1,a1.y, fmaf(b2,a2.y, fmaf(b3,a3.y, b4*a4.y))));
        o.z = fmaf(b0,a0.z, fmaf(b1,a1.z, fmaf(b2,a2.z, fmaf(b3,a3.z, b4*a4.z))));
        o.w = fmaf(b0,a0.w, fmaf(b1,a1.w, fmaf(b2,a2.w, fmaf(b3,a3.w, b4*a4.w))));
        reinterpret_cast<float4*>(out_edge + (size_t)(e0 + le) * D_DIM)[lane] = o;
    }
}

// ---------------------------------------------------------------------------
// Kernel 3: fused node-side GEMMs on tensor cores (mma.sync tf32).
// Per block: 64 rows x 128 cols. 8 warps as 2x4 (warp tile 32x32).
//  agg = bsum @ anchor_edge            (fp32, fused into staging)
//  h   = relu([px|agg] @ cd1_w + b1)   K=256
//  tv  = (px+agg) @ int_w              K=128  (kept in registers)
//  cs  = sigmoid(h @ cd2_w + b2)       K=128
//  out = px + cs * (tv + int_b)
// ---------------------------------------------------------------------------
#define TMR 64
#define SP  132     // A-array pitch (SP % 32 == 4 -> conflict-free frag loads)
#define WP  136     // weight-tile pitch (WP % 32 == 8 -> conflict-free B frags)
#define SMEM_FLOATS (3 * TMR * SP + 32 * WP)
#define SMEM_BYTES  (SMEM_FLOATS * 4)

__device__ __forceinline__ void mma_chunk(
    const float* __restrict__ Ab, int kof, const float* __restrict__ sW,
    int rbase, int nbase, int g, int tg, float acc[2][4][4])
{
#pragma unroll
    for (int ks = 0; ks < 4; ks++) {
        int k0 = ks * 8;
        uint32_t afr[2][4];
#pragma unroll
        for (int mi = 0; mi < 2; mi++) {
            const float* ap = &Ab[(rbase + mi * 16 + g) * SP + kof + k0 + tg];
            afr[mi][0] = f2tf(ap[0]);
            afr[mi][1] = f2tf(ap[8 * SP]);
            afr[mi][2] = f2tf(ap[4]);
            afr[mi][3] = f2tf(ap[8 * SP + 4]);
        }
        uint32_t bfr[4][2];
#pragma unroll
        for (int ni = 0; ni < 4; ni++) {
            const float* bp = &sW[(k0 + tg) * WP + nbase + ni * 8 + g];
            bfr[ni][0] = f2tf(bp[0]);
            bfr[ni][1] = f2tf(bp[4 * WP]);
        }
#pragma unroll
        for (int mi = 0; mi < 2; mi++)
#pragma unroll
            for (int ni = 0; ni < 4; ni++)
                mma_tf32(acc[mi][ni], afr[mi], bfr[ni]);
    }
}

__global__ __launch_bounds__(256, 1) void node_post_kernel(
    const float* __restrict__ anchor_edge,
    const float* __restrict__ cd1_w, const float* __restrict__ cd1_b,
    const float* __restrict__ cd2_w, const float* __restrict__ cd2_b,
    const float* __restrict__ int_w, const float* __restrict__ int_b,
    float* __restrict__ out_final)
{
    extern __shared__ float smem[];
    float* spx  = smem;                 // [64][SP]  node_px (fp32, kept exact)
    float* sagg = spx  + TMR * SP;      // [64][SP]  agg, later px+agg
    float* sh2  = sagg + TMR * SP;      // [64][SP]  h, later final
    float* sW   = sh2  + TMR * SP;      // [32][WP]  weight chunk

    int tid = threadIdx.x;
    int row0 = blockIdx.x * TMR;

    for (int idx = tid; idx < TMR * D_DIM; idx += 256) {
        int r = idx >> 7, c = idx & 127;
        int n = row0 + r;
        float px = 0.f, ag = 0.f;
        if (n < N_NODES) {
            px = g_node_px[(size_t)n * D_DIM + c];
#pragma unroll
            for (int a = 0; a < A_DIM; a++)
                ag = fmaf(g_bsum[n * A_DIM + a], anchor_edge[a * D_DIM + c], ag);
        }
        spx[r * SP + c]  = px;
        sagg[r * SP + c] = ag;
    }
    __syncthreads();

    int lane = tid & 31, wid = tid >> 5;
    int wm = wid >> 2, wn = wid & 3;       // 2 x 4 warp grid
    int g = lane >> 2, tg = lane & 3;
    int rbase = wm * 32;
    int nbase = wn * 32;

    float acc1[2][4][4];
#pragma unroll
    for (int mi = 0; mi < 2; mi++)
#pragma unroll
        for (int ni = 0; ni < 4; ni++)
#pragma unroll
            for (int q = 0; q < 4; q++) acc1[mi][ni][q] = 0.f;

    // ---- GEMM1: [px|agg] @ cd1_w, K=256 ----
    for (int kb = 0; kb < 256; kb += 32) {
        __syncthreads();
        for (int i = tid; i < 32 * 32; i += 256) {
            int r = i >> 5, c4 = (i & 31) << 2;
            float4 w4 = *reinterpret_cast<const float4*>(&cd1_w[(kb + r) * 128 + c4]);
            float* dpt = &sW[r * WP + c4];
            dpt[0] = w4.x; dpt[1] = w4.y; dpt[2] = w4.z; dpt[3] = w4.w;
        }
        __syncthreads();
        const float* Ab = (kb < 128) ? spx : sagg;
        mma_chunk(Ab, kb & 127, sW, rbase, nbase, g, tg, acc1);
    }

    // h = relu(acc1 + b1) -> sh2
#pragma unroll
    for (int mi = 0; mi < 2; mi++)
#pragma unroll
        for (int ni = 0; ni < 4; ni++) {
            int r0 = rbase + mi * 16 + g;
            int c0 = nbase + ni * 8 + 2 * tg;
            float b0v = cd1_b[c0], b1v = cd1_b[c0 + 1];
            sh2[r0 * SP + c0]           = fmaxf(acc1[mi][ni][0] + b0v, 0.f);
            sh2[r0 * SP + c0 + 1]       = fmaxf(acc1[mi][ni][1] + b1v, 0.f);
            sh2[(r0 + 8) * SP + c0]     = fmaxf(acc1[mi][ni][2] + b0v, 0.f);
            sh2[(r0 + 8) * SP + c0 + 1] = fmaxf(acc1[mi][ni][3] + b1v, 0.f);
        }
    __syncthreads();

    // sagg := px + agg (psum for GEMM3)
    for (int idx = tid; idx < TMR * D_DIM; idx += 256) {
        int r = idx >> 7, c = idx & 127;
        sagg[r * SP + c] += spx[r * SP + c];
    }

    // ---- GEMM3: psum @ int_w, K=128 -> tv (registers) ----
    float acc3[2][4][4];
#pragma unroll
    for (int mi = 0; mi < 2; mi++)
#pragma unroll
        for (int ni = 0; ni < 4; ni++)
#pragma unroll
            for (int q = 0; q < 4; q++) acc3[mi][ni][q] = 0.f;

    for (int kb = 0; kb < 128; kb += 32) {
        __syncthreads();
        for (int i = tid; i < 32 * 32; i += 256) {
            int r = i >> 5, c4 = (i & 31) << 2;
            float4 w4 = *reinterpret_cast<const float4*>(&int_w[(kb + r) * 128 + c4]);
            float* dpt = &sW[r * WP + c4];
            dpt[0] = w4.x; dpt[1] = w4.y; dpt[2] = w4.z; dpt[3] = w4.w;
        }
        __syncthreads();
        mma_chunk(sagg, kb, sW, rbase, nbase, g, tg, acc3);
    }

    // ---- GEMM2: h @ cd2_w, K=128 -> cs (registers) ----
    float acc2[2][4][4];
#pragma unroll
    for (int mi = 0; mi < 2; mi++)
#pragma unroll
        for (int ni = 0; ni < 4; ni++)
#pragma unroll
            for (int q = 0; q < 4; q++) acc2[mi][ni][q] = 0.f;

    for (int kb = 0; kb < 128; kb += 32) {
        __syncthreads();
        for (int i = tid; i < 32 * 32; i += 256) {
            int r = i >> 5, c4 = (i & 31) << 2;
            float4 w4 = *reinterpret_cast<const float4*>(&cd2_w[(kb + r) * 128 + c4]);
            float* dpt = &sW[r * WP + c4];
            dpt[0] = w4.x; dpt[1] = w4.y; dpt[2] = w4.z; dpt[3] = w4.w;
        }
        __syncthreads();
        mma_chunk(sh2, kb, sW, rbase, nbase, g, tg, acc2);
    }
    __syncthreads();   // all reads of sh2 done; safe to overwrite with final

    // final = px + sigmoid(acc2 + b2) * (acc3 + int_b)  -> sh2, then coalesced out
#pragma unroll
    for (int mi = 0; mi < 2; mi++)
#pragma unroll
        for (int ni = 0; ni < 4; ni++) {
            int r0 = rbase + mi * 16 + g;
            int c0 = nbase + ni * 8 + 2 * tg;
            float bc0 = cd2_b[c0], bc1 = cd2_b[c0 + 1];
            float bi0 = int_b[c0], bi1 = int_b[c0 + 1];
#pragma unroll
            for (int h = 0; h < 2; h++) {
                int rr = r0 + h * 8;
                float cs0 = 1.0f / (1.0f + __expf(-(acc2[mi][ni][2*h]   + bc0)));
                float cs1 = 1.0f / (1.0f + __expf(-(acc2[mi][ni][2*h+1] + bc1)));
                float tv0 = acc3[mi][ni][2*h]   + bi0;
                float tv1 = acc3[mi][ni][2*h+1] + bi1;
                sh2[rr * SP + c0]     = fmaf(cs0, tv0, spx[rr * SP + c0]);
                sh2[rr * SP + c0 + 1] = fmaf(cs1, tv1, spx[rr * SP + c0 + 1]);
            }
        }
    __syncthreads();

    for (int idx = tid; idx < TMR * 32; idx += 256) {
        int r = idx >> 5, c4 = (idx & 31) << 2;
        int n = row0 + r;
        if (n < N_NODES)
            *reinterpret_cast<float4*>(&out_final[(size_t)n * D_DIM + c4]) =
                *reinterpret_cast<const float4*>(&sh2[r * SP + c4]);
    }
}

// ---------------------------------------------------------------------------
extern "C" void kernel_launch(void* const* d_in, const int* in_sizes, int n_in,
                              void* d_out, int out_size)
{
    const float* x           = (const float*)d_in[0];
    const float* anchor_node = (const float*)d_in[1];
    const float* attn_w      = (const float*)d_in[2];
    const float* attn_b      = (const float*)d_in[3];
    const float* anchor_edge = (const float*)d_in[4];
    const float* w_w         = (const float*)d_in[5];
    const float* w_b         = (const float*)d_in[6];
    const float* cd1_w       = (const float*)d_in[7];
    const float* cd1_b       = (const float*)d_in[8];
    const float* cd2_w       = (const float*)d_in[9];
    const float* cd2_b       = (const float*)d_in[10];
    const float* int_w       = (const float*)d_in[11];
    const float* int_b       = (const float*)d_in[12];
    const int*   edge_index  = (const int*)d_in[13];
    float* outp = (float*)d_out;   // [0, N*D) = final_x, [N*D, ...) = edge_prompt

    node_pre_kernel<<<(N_NODES + 7) / 8, 256>>>(x, anchor_node, attn_w, attn_b, w_w);
    edge_kernel<<<E_EDGES / 256, 256>>>(edge_index, anchor_edge, w_b,
                                        outp + (size_t)N_NODES * D_DIM);
    cudaFuncSetAttribute(node_post_kernel,
                         cudaFuncAttributeMaxDynamicSharedMemorySize, SMEM_BYTES);
    node_post_kernel<<<(N_NODES + TMR - 1) / TMR, 256, SMEM_BYTES>>>(
        anchor_edge, cd1_w, cd1_b, cd2_w, cd2_b, int_w, int_b, outp);
}

// round 3
// speedup vs baseline: 2.6204x; 1.3451x over previous
#include <cuda_runtime.h>
#include <math.h>
#include <stdint.h>

#define N_NODES 50000
#define E_EDGES 800000
#define D_DIM   128
#define A_DIM   5

// Scratch (no allocations allowed in kernel_launch)
__device__ float g_node_px[N_NODES * D_DIM];  // node_px [N,128]
__device__ float g_s[N_NODES * 16];           // per node: s_src[5] @0, s_dst[5] @8 (padded)
__device__ float g_bsum[N_NODES * A_DIM];     // scattered sum of b vectors

__device__ __forceinline__ uint32_t f2tf(float f) {
    uint32_t r; asm("cvt.rna.tf32.f32 %0, %1;" : "=r"(r) : "f"(f)); return r;
}

__device__ __forceinline__ void mma_tf32(float* d, const uint32_t* a, const uint32_t* b) {
    asm volatile("mma.sync.aligned.m16n8k8.row.col.f32.tf32.tf32.f32 "
        "{%0,%1,%2,%3}, {%4,%5,%6,%7}, {%8,%9}, {%0,%1,%2,%3};"
        : "+f"(d[0]), "+f"(d[1]), "+f"(d[2]), "+f"(d[3])
        : "r"(a[0]), "r"(a[1]), "r"(a[2]), "r"(a[3]), "r"(b[0]), "r"(b[1]));
}

// ---------------------------------------------------------------------------
// Kernel 1: per-node precompute. Grid-stride warp-per-node, weights in
// REGISTERS (loaded once from a per-block smem transpose).
// ---------------------------------------------------------------------------
#define PRE_BLOCKS 592

__global__ __launch_bounds__(256) void node_pre_kernel(
    const float* __restrict__ x,
    const float* __restrict__ anchor_node,
    const float* __restrict__ attn_w,
    const float* __restrict__ attn_b,
    const float* __restrict__ w_w)
{
    __shared__ float shT[20 * D_DIM];   // attnT | wsT | wdT | anchor (each [5][128])
    __shared__ float sh_ab[8];

    int tid = threadIdx.x;
    for (int i = tid; i < 640; i += 256) {
        int a = i >> 7, d = i & 127;
        shT[a * 128 + d]        = attn_w[d * A_DIM + a];
        shT[640 + a * 128 + d]  = w_w[d * A_DIM + a];
        shT[1280 + a * 128 + d] = w_w[(128 + d) * A_DIM + a];
        shT[1920 + i]           = anchor_node[i];
    }
    if (tid < A_DIM) sh_ab[tid] = attn_b[tid];
    __syncthreads();

    int lane = tid & 31;
    int wid  = tid >> 5;
    int p0   = lane * 4;

    // hoist all weights into registers (per-lane slice)
    float4 wa[A_DIM], ws[A_DIM], wd[A_DIM], an[A_DIM];
    float ab[A_DIM];
#pragma unroll
    for (int c = 0; c < A_DIM; c++) {
        wa[c] = *reinterpret_cast<const float4*>(&shT[c * 128 + p0]);
        ws[c] = *reinterpret_cast<const float4*>(&shT[640 + c * 128 + p0]);
        wd[c] = *reinterpret_cast<const float4*>(&shT[1280 + c * 128 + p0]);
        an[c] = *reinterpret_cast<const float4*>(&shT[1920 + c * 128 + p0]);
        ab[c] = sh_ab[c];
    }

    int n0 = blockIdx.x * 8 + wid;
    int stride = PRE_BLOCKS * 8;

    for (int n = n0; n < N_NODES; n += stride) {
        float4 xv = reinterpret_cast<const float4*>(x + (size_t)n * D_DIM)[lane];

        float aA[A_DIM], aS[A_DIM], aD[A_DIM];
#pragma unroll
        for (int c = 0; c < A_DIM; c++) {
            aA[c] = fmaf(xv.x, wa[c].x, fmaf(xv.y, wa[c].y, fmaf(xv.z, wa[c].z, xv.w * wa[c].w)));
            aS[c] = fmaf(xv.x, ws[c].x, fmaf(xv.y, ws[c].y, fmaf(xv.z, ws[c].z, xv.w * ws[c].w)));
            aD[c] = fmaf(xv.x, wd[c].x, fmaf(xv.y, wd[c].y, fmaf(xv.z, wd[c].z, xv.w * wd[c].w)));
        }
#pragma unroll
        for (int off = 16; off > 0; off >>= 1) {
#pragma unroll
            for (int c = 0; c < A_DIM; c++) {
                aA[c] += __shfl_xor_sync(0xffffffffu, aA[c], off);
                aS[c] += __shfl_xor_sync(0xffffffffu, aS[c], off);
                aD[c] += __shfl_xor_sync(0xffffffffu, aD[c], off);
            }
        }

        float wgt[A_DIM];
        float m = -1e30f;
#pragma unroll
        for (int c = 0; c < A_DIM; c++) { wgt[c] = aA[c] + ab[c]; m = fmaxf(m, wgt[c]); }
        float ssum = 0.f;
#pragma unroll
        for (int c = 0; c < A_DIM; c++) { wgt[c] = __expf(wgt[c] - m); ssum += wgt[c]; }
        float inv = 1.0f / ssum;
#pragma unroll
        for (int c = 0; c < A_DIM; c++) wgt[c] *= inv;

        float4 o = xv;
#pragma unroll
        for (int c = 0; c < A_DIM; c++) {
            o.x = fmaf(wgt[c], an[c].x, o.x);
            o.y = fmaf(wgt[c], an[c].y, o.y);
            o.z = fmaf(wgt[c], an[c].z, o.z);
            o.w = fmaf(wgt[c], an[c].w, o.w);
        }
        reinterpret_cast<float4*>(g_node_px + (size_t)n * D_DIM)[lane] = o;

        if (lane == 0) {
#pragma unroll
            for (int c = 0; c < A_DIM; c++) {
                g_s[n * 16 + c]     = aS[c];
                g_s[n * 16 + 8 + c] = aD[c];
                g_bsum[n * A_DIM + c] = 0.f;
            }
        }
    }
}

// ---------------------------------------------------------------------------
// Kernel 2: edges. No smem, no __syncthreads.
// Phase A: thread-per-edge softmax + 10 REDs. Phase B: warp-per-edge store,
// b broadcast via __shfl (SHFL pipe, not LSU), anchor_edge in registers,
// streaming stores (__stcs) for edge_prompt.
// ---------------------------------------------------------------------------
__global__ __launch_bounds__(256) void edge_kernel(
    const int* __restrict__ edge_index,
    const float* __restrict__ anchor_edge,
    const float* __restrict__ w_b,
    float* __restrict__ out_edge)
{
    int tid  = threadIdx.x;
    int lane = tid & 31;
    int wid  = tid >> 5;
    int p0   = lane * 4;

    // per-lane anchor_edge slice in registers (coalesced loads, L2-broadcast)
    float4 ae[A_DIM];
    float  wb[A_DIM];
#pragma unroll
    for (int c = 0; c < A_DIM; c++) {
        ae[c] = __ldg(&reinterpret_cast<const float4*>(anchor_edge + c * D_DIM)[lane]);
        wb[c] = __ldg(&w_b[c]);
    }

    int e = blockIdx.x * 256 + tid;
    int src = edge_index[e];
    int dst = edge_index[E_EDGES + e];

    float4 s03 = *reinterpret_cast<const float4*>(&g_s[src * 16]);
    float  s4  = g_s[src * 16 + 4];
    float4 d03 = *reinterpret_cast<const float4*>(&g_s[dst * 16 + 8]);
    float  d4  = g_s[dst * 16 + 12];

    float b[A_DIM];
    b[0] = s03.x + d03.x + wb[0];
    b[1] = s03.y + d03.y + wb[1];
    b[2] = s03.z + d03.z + wb[2];
    b[3] = s03.w + d03.w + wb[3];
    b[4] = s4    + d4    + wb[4];

    float m = -1e30f;
#pragma unroll
    for (int c = 0; c < A_DIM; c++) {
        b[c] = (b[c] > 0.f) ? b[c] : 0.01f * b[c];   // leaky_relu
        m = fmaxf(m, b[c]);
    }
    float ssum = 0.f;
#pragma unroll
    for (int c = 0; c < A_DIM; c++) { b[c] = __expf(b[c] - m); ssum += b[c]; }
    float inv = 1.0f / ssum;
#pragma unroll
    for (int c = 0; c < A_DIM; c++) {
        b[c] *= inv;
        atomicAdd(&g_bsum[src * A_DIM + c], b[c]);
        atomicAdd(&g_bsum[dst * A_DIM + c], b[c]);
    }

    // Phase B: warp writes its own 32 edges, b via shuffle
    size_t ebase = (size_t)blockIdx.x * 256 + wid * 32;
#pragma unroll 4
    for (int le = 0; le < 32; le++) {
        float b0 = __shfl_sync(0xffffffffu, b[0], le);
        float b1 = __shfl_sync(0xffffffffu, b[1], le);
        float b2 = __shfl_sync(0xffffffffu, b[2], le);
        float b3 = __shfl_sync(0xffffffffu, b[3], le);
        float b4 = __shfl_sync(0xffffffffu, b[4], le);
        float4 o;
        o.x = fmaf(b0,ae[0].x, fmaf(b1,ae[1].x, fmaf(b2,ae[2].x, fmaf(b3,ae[3].x, b4*ae[4].x))));
        o.y = fmaf(b0,ae[0].y, fmaf(b1,ae[1].y, fmaf(b2,ae[2].y, fmaf(b3,ae[3].y, b4*ae[4].y))));
        o.z = fmaf(b0,ae[0].z, fmaf(b1,ae[1].z, fmaf(b2,ae[2].z, fmaf(b3,ae[3].z, b4*ae[4].z))));
        o.w = fmaf(b0,ae[0].w, fmaf(b1,ae[1].w, fmaf(b2,ae[2].w, fmaf(b3,ae[3].w, b4*ae[4].w))));
        __stcs(&reinterpret_cast<float4*>(out_edge + (ebase + le) * D_DIM)[lane], o);
    }
}

// ---------------------------------------------------------------------------
// Kernel 3: fused node-side GEMMs (mma.sync tf32), 128 rows x 128 cols/block.
// A and B tiles pre-rounded to tf32 ONCE at staging (frag load = plain LDS +
// bit-cast). px/agg kept as separate tf32 tiles; psum formed at frag time for
// GEMM3. Exact-fp32 px re-read from global for the final add.
// ---------------------------------------------------------------------------
#define TMR 128
#define SP  132     // A pitch: SP%32==4 -> conflict-free A frags
#define WP  136     // B pitch: WP%32==8 -> conflict-free B frags
#define SMEM_FLOATS (3 * TMR * SP + 32 * WP)
#define SMEM_BYTES  (SMEM_FLOATS * 4)

__device__ __forceinline__ void ldA_pt(const float* __restrict__ A, int row, int kcol,
                                       uint32_t afr[4]) {
    const float* ap = &A[row * SP + kcol];
    afr[0] = __float_as_uint(ap[0]);
    afr[1] = __float_as_uint(ap[8 * SP]);
    afr[2] = __float_as_uint(ap[4]);
    afr[3] = __float_as_uint(ap[8 * SP + 4]);
}

__device__ __forceinline__ void chunk_pt(
    const float* __restrict__ A, int kof, const float* __restrict__ sW,
    int rbase, int nbase, int g, int tg, float acc[4][4][4])
{
#pragma unroll
    for (int ks = 0; ks < 4; ks++) {
        int k0 = ks * 8;
        uint32_t afr[4][4];
#pragma unroll
        for (int mi = 0; mi < 4; mi++)
            ldA_pt(A, rbase + mi * 16 + g, kof + k0 + tg, afr[mi]);
        uint32_t bfr[4][2];
#pragma unroll
        for (int ni = 0; ni < 4; ni++) {
            const float* bp = &sW[(k0 + tg) * WP + nbase + ni * 8 + g];
            bfr[ni][0] = __float_as_uint(bp[0]);
            bfr[ni][1] = __float_as_uint(bp[4 * WP]);
        }
#pragma unroll
        for (int mi = 0; mi < 4; mi++)
#pragma unroll
            for (int ni = 0; ni < 4; ni++)
                mma_tf32(acc[mi][ni], afr[mi], bfr[ni]);
    }
}

__device__ __forceinline__ void chunk_sum(
    const float* __restrict__ A0, const float* __restrict__ A1, int kof,
    const float* __restrict__ sW, int rbase, int nbase, int g, int tg,
    float acc[4][4][4])
{
#pragma unroll
    for (int ks = 0; ks < 4; ks++) {
        int k0 = ks * 8;
        uint32_t afr[4][4];
#pragma unroll
        for (int mi = 0; mi < 4; mi++) {
            int off = (rbase + mi * 16 + g) * SP + kof + k0 + tg;
            afr[mi][0] = f2tf(A0[off]           + A1[off]);
            afr[mi][1] = f2tf(A0[off + 8 * SP]  + A1[off + 8 * SP]);
            afr[mi][2] = f2tf(A0[off + 4]       + A1[off + 4]);
            afr[mi][3] = f2tf(A0[off + 8*SP + 4]+ A1[off + 8*SP + 4]);
        }
        uint32_t bfr[4][2];
#pragma unroll
        for (int ni = 0; ni < 4; ni++) {
            const float* bp = &sW[(k0 + tg) * WP + nbase + ni * 8 + g];
            bfr[ni][0] = __float_as_uint(bp[0]);
            bfr[ni][1] = __float_as_uint(bp[4 * WP]);
        }
#pragma unroll
        for (int mi = 0; mi < 4; mi++)
#pragma unroll
            for (int ni = 0; ni < 4; ni++)
                mma_tf32(acc[mi][ni], afr[mi], bfr[ni]);
    }
}

__global__ __launch_bounds__(256, 1) void node_post_kernel(
    const float* __restrict__ anchor_edge,
    const float* __restrict__ cd1_w, const float* __restrict__ cd1_b,
    const float* __restrict__ cd2_w, const float* __restrict__ cd2_b,
    const float* __restrict__ int_w, const float* __restrict__ int_b,
    float* __restrict__ out_final)
{
    extern __shared__ float smem[];
    float* sPX = smem;                  // [128][SP] tf32(px)
    float* sAG = sPX + TMR * SP;        // [128][SP] tf32(agg)
    float* sH  = sAG + TMR * SP;        // [128][SP] tf32(h), later final-partial
    float* sW  = sH  + TMR * SP;        // [32][WP] weights; also bsum/anchor staging

    int tid = threadIdx.x;
    int row0 = blockIdx.x * TMR;

    // stage bsum rows + anchor_edge into sW scratch
    for (int i = tid; i < TMR * A_DIM; i += 256) {
        int n = row0 + i / A_DIM;
        sW[i] = (n < N_NODES) ? g_bsum[n * A_DIM + i % A_DIM] : 0.f;
    }
    for (int i = tid; i < A_DIM * D_DIM; i += 256) sW[TMR * A_DIM + i] = anchor_edge[i];
    __syncthreads();

    // stage tf32(px), tf32(agg)
    for (int idx = tid; idx < TMR * D_DIM; idx += 256) {
        int r = idx >> 7, c = idx & 127;
        int n = row0 + r;
        float px = (n < N_NODES) ? g_node_px[(size_t)n * D_DIM + c] : 0.f;
        float ag = 0.f;
#pragma unroll
        for (int a = 0; a < A_DIM; a++)
            ag = fmaf(sW[r * A_DIM + a], sW[TMR * A_DIM + a * D_DIM + c], ag);
        sPX[r * SP + c] = __uint_as_float(f2tf(px));
        sAG[r * SP + c] = __uint_as_float(f2tf(ag));
    }

    int lane = tid & 31, wid = tid >> 5;
    int wm = wid >> 2, wn = wid & 3;
    int g = lane >> 2, tg = lane & 3;
    int rbase = wm * 64;
    int nbase = wn * 32;

    float acc1[4][4][4];
#pragma unroll
    for (int mi = 0; mi < 4; mi++)
#pragma unroll
        for (int ni = 0; ni < 4; ni++)
#pragma unroll
            for (int q = 0; q < 4; q++) acc1[mi][ni][q] = 0.f;

    // ---- GEMM1: [px|agg] @ cd1_w, K=256 ----
    for (int kb = 0; kb < 256; kb += 32) {
        __syncthreads();
        for (int i = tid; i < 32 * 32; i += 256) {
            int r = i >> 5, c4 = (i & 31) << 2;
            float4 w4 = *reinterpret_cast<const float4*>(&cd1_w[(kb + r) * 128 + c4]);
            float* dpt = &sW[r * WP + c4];
            dpt[0] = __uint_as_float(f2tf(w4.x));
            dpt[1] = __uint_as_float(f2tf(w4.y));
            dpt[2] = __uint_as_float(f2tf(w4.z));
            dpt[3] = __uint_as_float(f2tf(w4.w));
        }
        __syncthreads();
        const float* Ab = (kb < 128) ? sPX : sAG;
        chunk_pt(Ab, kb & 127, sW, rbase, nbase, g, tg, acc1);
    }

    // h = tf32(relu(acc1 + b1)) -> sH
#pragma unroll
    for (int mi = 0; mi < 4; mi++)
#pragma unroll
        for (int ni = 0; ni < 4; ni++) {
            int r0 = rbase + mi * 16 + g;
            int c0 = nbase + ni * 8 + 2 * tg;
            float b0v = cd1_b[c0], b1v = cd1_b[c0 + 1];
            sH[r0 * SP + c0]           = __uint_as_float(f2tf(fmaxf(acc1[mi][ni][0] + b0v, 0.f)));
            sH[r0 * SP + c0 + 1]       = __uint_as_float(f2tf(fmaxf(acc1[mi][ni][1] + b1v, 0.f)));
            sH[(r0 + 8) * SP + c0]     = __uint_as_float(f2tf(fmaxf(acc1[mi][ni][2] + b0v, 0.f)));
            sH[(r0 + 8) * SP + c0 + 1] = __uint_as_float(f2tf(fmaxf(acc1[mi][ni][3] + b1v, 0.f)));
        }

    // ---- GEMM3: (px+agg) @ int_w, K=128 -> tv ----
    float acc3[4][4][4];
#pragma unroll
    for (int mi = 0; mi < 4; mi++)
#pragma unroll
        for (int ni = 0; ni < 4; ni++)
#pragma unroll
            for (int q = 0; q < 4; q++) acc3[mi][ni][q] = 0.f;

    for (int kb = 0; kb < 128; kb += 32) {
        __syncthreads();
        for (int i = tid; i < 32 * 32; i += 256) {
            int r = i >> 5, c4 = (i & 31) << 2;
            float4 w4 = *reinterpret_cast<const float4*>(&int_w[(kb + r) * 128 + c4]);
            float* dpt = &sW[r * WP + c4];
            dpt[0] = __uint_as_float(f2tf(w4.x));
            dpt[1] = __uint_as_float(f2tf(w4.y));
            dpt[2] = __uint_as_float(f2tf(w4.z));
            dpt[3] = __uint_as_float(f2tf(w4.w));
        }
        __syncthreads();
        chunk_sum(sPX, sAG, kb, sW, rbase, nbase, g, tg, acc3);
    }

    // ---- GEMM2: h @ cd2_w, K=128 -> cs ----
    float acc2[4][4][4];
#pragma unroll
    for (int mi = 0; mi < 4; mi++)
#pragma unroll
        for (int ni = 0; ni < 4; ni++)
#pragma unroll
            for (int q = 0; q < 4; q++) acc2[mi][ni][q] = 0.f;

    for (int kb = 0; kb < 128; kb += 32) {
        __syncthreads();
        for (int i = tid; i < 32 * 32; i += 256) {
            int r = i >> 5, c4 = (i & 31) << 2;
            float4 w4 = *reinterpret_cast<const float4*>(&cd2_w[(kb + r) * 128 + c4]);
            float* dpt = &sW[r * WP + c4];
            dpt[0] = __uint_as_float(f2tf(w4.x));
            dpt[1] = __uint_as_float(f2tf(w4.y));
            dpt[2] = __uint_as_float(f2tf(w4.z));
            dpt[3] = __uint_as_float(f2tf(w4.w));
        }
        __syncthreads();
        chunk_pt(sH, kb, sW, rbase, nbase, g, tg, acc2);
    }
    __syncthreads();   // all sH (h) reads done; safe to overwrite

    // final-partial = sigmoid(acc2+b2) * (acc3+int_b)  -> sH
#pragma unroll
    for (int mi = 0; mi < 4; mi++)
#pragma unroll
        for (int ni = 0; ni < 4; ni++) {
            int r0 = rbase + mi * 16 + g;
            int c0 = nbase + ni * 8 + 2 * tg;
            float bc0 = cd2_b[c0], bc1 = cd2_b[c0 + 1];
            float bi0 = int_b[c0], bi1 = int_b[c0 + 1];
#pragma unroll
            for (int h = 0; h < 2; h++) {
                int rr = r0 + h * 8;
                float cs0 = 1.0f / (1.0f + __expf(-(acc2[mi][ni][2*h]   + bc0)));
                float cs1 = 1.0f / (1.0f + __expf(-(acc2[mi][ni][2*h+1] + bc1)));
                sH[rr * SP + c0]     = cs0 * (acc3[mi][ni][2*h]   + bi0);
                sH[rr * SP + c0 + 1] = cs1 * (acc3[mi][ni][2*h+1] + bi1);
            }
        }
    __syncthreads();

    // out = exact px (global) + final-partial, coalesced float4
    for (int idx = tid; idx < TMR * 32; idx += 256) {
        int r = idx >> 5, c4 = (idx & 31) << 2;
        int n = row0 + r;
        if (n < N_NODES) {
            float4 px4 = *reinterpret_cast<const float4*>(&g_node_px[(size_t)n * D_DIM + c4]);
            const float* hp = &sH[r * SP + c4];
            float4 o = {px4.x + hp[0], px4.y + hp[1], px4.z + hp[2], px4.w + hp[3]};
            *reinterpret_cast<float4*>(&out_final[(size_t)n * D_DIM + c4]) = o;
        }
    }
}

// ---------------------------------------------------------------------------
extern "C" void kernel_launch(void* const* d_in, const int* in_sizes, int n_in,
                              void* d_out, int out_size)
{
    const float* x           = (const float*)d_in[0];
    const float* anchor_node = (const float*)d_in[1];
    const float* attn_w      = (const float*)d_in[2];
    const float* attn_b      = (const float*)d_in[3];
    const float* anchor_edge = (const float*)d_in[4];
    const float* w_w         = (const float*)d_in[5];
    const float* w_b         = (const float*)d_in[6];
    const float* cd1_w       = (const float*)d_in[7];
    const float* cd1_b       = (const float*)d_in[8];
    const float* cd2_w       = (const float*)d_in[9];
    const float* cd2_b       = (const float*)d_in[10];
    const float* int_w       = (const float*)d_in[11];
    const float* int_b       = (const float*)d_in[12];
    const int*   edge_index  = (const int*)d_in[13];
    float* outp = (float*)d_out;   // [0, N*D) = final_x, [N*D, ...) = edge_prompt

    node_pre_kernel<<<PRE_BLOCKS, 256>>>(x, anchor_node, attn_w, attn_b, w_w);
    edge_kernel<<<E_EDGES / 256, 256>>>(edge_index, anchor_edge, w_b,
                                        outp + (size_t)N_NODES * D_DIM);
    cudaFuncSetAttribute(node_post_kernel,
                         cudaFuncAttributeMaxDynamicSharedMemorySize, SMEM_BYTES);
    node_post_kernel<<<(N_NODES + TMR - 1) / TMR, 256, SMEM_BYTES>>>(
        anchor_edge, cd1_w, cd1_b, cd2_w, cd2_b, int_w, int_b, outp);
}

// round 4
// speedup vs baseline: 2.8182x; 1.0755x over previous
#include <cuda_runtime.h>
#include <math.h>
#include <stdint.h>

#define N_NODES 50000
#define E_EDGES 800000
#define D_DIM   128
#define A_DIM   5

// Scratch (no allocations allowed in kernel_launch)
__device__ float g_node_px[N_NODES * D_DIM];       // node_px [N,128]
__device__ float g_s[N_NODES * 16];                // s_src[5] @0, s_dst[5] @8
__device__ float g_bsum[(N_NODES + 128) * 8];      // padded: b-sum per node, 8-stride

__device__ __forceinline__ uint32_t f2tf(float f) {
    uint32_t r; asm("cvt.rna.tf32.f32 %0, %1;" : "=r"(r) : "f"(f)); return r;
}

__device__ __forceinline__ void mma_tf32(float* d, const uint32_t* a, const uint32_t* b) {
    asm volatile("mma.sync.aligned.m16n8k8.row.col.f32.tf32.tf32.f32 "
        "{%0,%1,%2,%3}, {%4,%5,%6,%7}, {%8,%9}, {%0,%1,%2,%3};"
        : "+f"(d[0]), "+f"(d[1]), "+f"(d[2]), "+f"(d[3])
        : "r"(a[0]), "r"(a[1]), "r"(a[2]), "r"(a[3]), "r"(b[0]), "r"(b[1]));
}

// ---------------------------------------------------------------------------
// Kernel 1: per-node precompute. 8-lane groups: each warp = 4 nodes, each
// lane owns a 16-float slice. Reduction = 3 butterfly rounds (not 5).
// Weights stay in smem (broadcast LDS), keeping regs low for occupancy.
// ---------------------------------------------------------------------------
__global__ __launch_bounds__(256) void node_pre_kernel(
    const float* __restrict__ x,
    const float* __restrict__ anchor_node,
    const float* __restrict__ attn_w,
    const float* __restrict__ attn_b,
    const float* __restrict__ w_w)
{
    __shared__ float shT[20 * D_DIM];   // attnT | wsT | wdT | anchor (each [5][128])
    __shared__ float sh_ab[8];

    int tid = threadIdx.x;
    for (int i = tid; i < 640; i += 256) {
        int a = i >> 7, d = i & 127;
        shT[a * 128 + d]        = attn_w[d * A_DIM + a];
        shT[640 + a * 128 + d]  = w_w[d * A_DIM + a];
        shT[1280 + a * 128 + d] = w_w[(128 + d) * A_DIM + a];
        shT[1920 + i]           = anchor_node[i];
    }
    if (tid < A_DIM) sh_ab[tid] = attn_b[tid];
    __syncthreads();

    int lane = tid & 31;
    int wid  = tid >> 5;
    int li   = lane & 7;       // lane within 8-lane group
    int gq   = lane >> 3;      // group (node) within warp
    int p0   = li * 16;        // this lane's 16-float slice

    int n = blockIdx.x * 32 + wid * 4 + gq;
    if (n >= N_NODES) return;

    float4 xr[4];
#pragma unroll
    for (int j = 0; j < 4; j++)
        xr[j] = *reinterpret_cast<const float4*>(&x[(size_t)n * D_DIM + p0 + 4 * j]);

    float aA[A_DIM], aS[A_DIM], aD[A_DIM];
#pragma unroll
    for (int c = 0; c < A_DIM; c++) { aA[c] = 0.f; aS[c] = 0.f; aD[c] = 0.f; }

#pragma unroll
    for (int c = 0; c < A_DIM; c++) {
#pragma unroll
        for (int j = 0; j < 4; j++) {
            float4 wa = *reinterpret_cast<const float4*>(&shT[c * 128 + p0 + 4 * j]);
            float4 ws = *reinterpret_cast<const float4*>(&shT[640 + c * 128 + p0 + 4 * j]);
            float4 wd = *reinterpret_cast<const float4*>(&shT[1280 + c * 128 + p0 + 4 * j]);
            aA[c] = fmaf(xr[j].x, wa.x, fmaf(xr[j].y, wa.y, fmaf(xr[j].z, wa.z, fmaf(xr[j].w, wa.w, aA[c]))));
            aS[c] = fmaf(xr[j].x, ws.x, fmaf(xr[j].y, ws.y, fmaf(xr[j].z, ws.z, fmaf(xr[j].w, ws.w, aS[c]))));
            aD[c] = fmaf(xr[j].x, wd.x, fmaf(xr[j].y, wd.y, fmaf(xr[j].z, wd.z, fmaf(xr[j].w, wd.w, aD[c]))));
        }
    }
#pragma unroll
    for (int off = 4; off > 0; off >>= 1) {
#pragma unroll
        for (int c = 0; c < A_DIM; c++) {
            aA[c] += __shfl_xor_sync(0xffffffffu, aA[c], off);
            aS[c] += __shfl_xor_sync(0xffffffffu, aS[c], off);
            aD[c] += __shfl_xor_sync(0xffffffffu, aD[c], off);
        }
    }

    float wgt[A_DIM];
    float m = -1e30f;
#pragma unroll
    for (int c = 0; c < A_DIM; c++) { wgt[c] = aA[c] + sh_ab[c]; m = fmaxf(m, wgt[c]); }
    float ssum = 0.f;
#pragma unroll
    for (int c = 0; c < A_DIM; c++) { wgt[c] = __expf(wgt[c] - m); ssum += wgt[c]; }
    float inv = 1.0f / ssum;
#pragma unroll
    for (int c = 0; c < A_DIM; c++) wgt[c] *= inv;

#pragma unroll
    for (int j = 0; j < 4; j++) {
        float4 o = xr[j];
#pragma unroll
        for (int c = 0; c < A_DIM; c++) {
            float4 an = *reinterpret_cast<const float4*>(&shT[1920 + c * 128 + p0 + 4 * j]);
            o.x = fmaf(wgt[c], an.x, o.x);
            o.y = fmaf(wgt[c], an.y, o.y);
            o.z = fmaf(wgt[c], an.z, o.z);
            o.w = fmaf(wgt[c], an.w, o.w);
        }
        *reinterpret_cast<float4*>(&g_node_px[(size_t)n * D_DIM + p0 + 4 * j]) = o;
    }

    if (li == 0) {
        float4 sv = {aS[0], aS[1], aS[2], aS[3]};
        float4 dv = {aD[0], aD[1], aD[2], aD[3]};
        *reinterpret_cast<float4*>(&g_s[n * 16])     = sv;
        g_s[n * 16 + 4]                              = aS[4];
        *reinterpret_cast<float4*>(&g_s[n * 16 + 8]) = dv;
        g_s[n * 16 + 12]                             = aD[4];
        float4 z = {0.f, 0.f, 0.f, 0.f};
        *reinterpret_cast<float4*>(&g_bsum[n * 8])     = z;
        *reinterpret_cast<float4*>(&g_bsum[n * 8 + 4]) = z;
    }
}

// ---------------------------------------------------------------------------
// Kernel 2: edges. Thread-per-edge softmax + VECTOR reds (v4 + scalar per
// endpoint: 4 RED ops instead of 10). Warp-per-edge coalesced streaming store
// of edge_prompt; b broadcast via shuffles; anchor_edge in registers.
// ---------------------------------------------------------------------------
__global__ __launch_bounds__(256) void edge_kernel(
    const int* __restrict__ edge_index,
    const float* __restrict__ anchor_edge,
    const float* __restrict__ w_b,
    float* __restrict__ out_edge)
{
    int tid  = threadIdx.x;
    int lane = tid & 31;
    int wid  = tid >> 5;

    float4 ae[A_DIM];
    float  wb[A_DIM];
#pragma unroll
    for (int c = 0; c < A_DIM; c++) {
        ae[c] = __ldg(&reinterpret_cast<const float4*>(anchor_edge + c * D_DIM)[lane]);
        wb[c] = __ldg(&w_b[c]);
    }

    int e = blockIdx.x * 256 + tid;
    int src = edge_index[e];
    int dst = edge_index[E_EDGES + e];

    float4 s03 = *reinterpret_cast<const float4*>(&g_s[src * 16]);
    float  s4  = g_s[src * 16 + 4];
    float4 d03 = *reinterpret_cast<const float4*>(&g_s[dst * 16 + 8]);
    float  d4  = g_s[dst * 16 + 12];

    float b[A_DIM];
    b[0] = s03.x + d03.x + wb[0];
    b[1] = s03.y + d03.y + wb[1];
    b[2] = s03.z + d03.z + wb[2];
    b[3] = s03.w + d03.w + wb[3];
    b[4] = s4    + d4    + wb[4];

    float m = -1e30f;
#pragma unroll
    for (int c = 0; c < A_DIM; c++) {
        b[c] = (b[c] > 0.f) ? b[c] : 0.01f * b[c];   // leaky_relu
        m = fmaxf(m, b[c]);
    }
    float ssum = 0.f;
#pragma unroll
    for (int c = 0; c < A_DIM; c++) { b[c] = __expf(b[c] - m); ssum += b[c]; }
    float inv = 1.0f / ssum;
#pragma unroll
    for (int c = 0; c < A_DIM; c++) b[c] *= inv;

    {
        float* ps = &g_bsum[(size_t)src * 8];
        float* pd = &g_bsum[(size_t)dst * 8];
        asm volatile("red.global.add.v4.f32 [%0], {%1,%2,%3,%4};"
                     :: "l"(ps), "f"(b[0]), "f"(b[1]), "f"(b[2]), "f"(b[3]) : "memory");
        asm volatile("red.global.add.f32 [%0+16], %1;"
                     :: "l"(ps), "f"(b[4]) : "memory");
        asm volatile("red.global.add.v4.f32 [%0], {%1,%2,%3,%4};"
                     :: "l"(pd), "f"(b[0]), "f"(b[1]), "f"(b[2]), "f"(b[3]) : "memory");
        asm volatile("red.global.add.f32 [%0+16], %1;"
                     :: "l"(pd), "f"(b[4]) : "memory");
    }

    // Phase B: warp stores its own 32 edges; b via shuffle broadcast
    size_t ebase = (size_t)blockIdx.x * 256 + wid * 32;
#pragma unroll 4
    for (int le = 0; le < 32; le++) {
        float b0 = __shfl_sync(0xffffffffu, b[0], le);
        float b1 = __shfl_sync(0xffffffffu, b[1], le);
        float b2 = __shfl_sync(0xffffffffu, b[2], le);
        float b3 = __shfl_sync(0xffffffffu, b[3], le);
        float b4 = __shfl_sync(0xffffffffu, b[4], le);
        float4 o;
        o.x = fmaf(b0,ae[0].x, fmaf(b1,ae[1].x, fmaf(b2,ae[2].x, fmaf(b3,ae[3].x, b4*ae[4].x))));
        o.y = fmaf(b0,ae[0].y, fmaf(b1,ae[1].y, fmaf(b2,ae[2].y, fmaf(b3,ae[3].y, b4*ae[4].y))));
        o.z = fmaf(b0,ae[0].z, fmaf(b1,ae[1].z, fmaf(b2,ae[2].z, fmaf(b3,ae[3].z, b4*ae[4].z))));
        o.w = fmaf(b0,ae[0].w, fmaf(b1,ae[1].w, fmaf(b2,ae[2].w, fmaf(b3,ae[3].w, b4*ae[4].w))));
        __stcs(&reinterpret_cast<float4*>(out_edge + (ebase + le) * D_DIM)[lane], o);
    }
}

// ---------------------------------------------------------------------------
// Kernel 3: fused node-side GEMMs (mma tf32), 128x128 per block, with
// register double-buffered weight chunks (next chunk preloaded during MMAs).
// ---------------------------------------------------------------------------
#define TMR 128
#define SP  132
#define WP  136
#define SMEM_FLOATS (3 * TMR * SP + 32 * WP)
#define SMEM_BYTES  (SMEM_FLOATS * 4)

__device__ __forceinline__ void w_preload(const float* __restrict__ W, int kb,
                                          int tid, float4 w[4]) {
#pragma unroll
    for (int j = 0; j < 4; j++) {
        int i = tid + j * 256;
        int r = i >> 5, c4 = (i & 31) << 2;
        w[j] = *reinterpret_cast<const float4*>(&W[(kb + r) * 128 + c4]);
    }
}

__device__ __forceinline__ void w_commit(float* __restrict__ sW, int tid,
                                         const float4 w[4]) {
#pragma unroll
    for (int j = 0; j < 4; j++) {
        int i = tid + j * 256;
        int r = i >> 5, c4 = (i & 31) << 2;
        float* d = &sW[r * WP + c4];
        d[0] = __uint_as_float(f2tf(w[j].x));
        d[1] = __uint_as_float(f2tf(w[j].y));
        d[2] = __uint_as_float(f2tf(w[j].z));
        d[3] = __uint_as_float(f2tf(w[j].w));
    }
}

__device__ __forceinline__ void ldA_pt(const float* __restrict__ A, int row, int kcol,
                                       uint32_t afr[4]) {
    const float* ap = &A[row * SP + kcol];
    afr[0] = __float_as_uint(ap[0]);
    afr[1] = __float_as_uint(ap[8 * SP]);
    afr[2] = __float_as_uint(ap[4]);
    afr[3] = __float_as_uint(ap[8 * SP + 4]);
}

__device__ __forceinline__ void chunk_pt(
    const float* __restrict__ A, int kof, const float* __restrict__ sW,
    int rbase, int nbase, int g, int tg, float acc[4][4][4])
{
#pragma unroll
    for (int ks = 0; ks < 4; ks++) {
        int k0 = ks * 8;
        uint32_t afr[4][4];
#pragma unroll
        for (int mi = 0; mi < 4; mi++)
            ldA_pt(A, rbase + mi * 16 + g, kof + k0 + tg, afr[mi]);
        uint32_t bfr[4][2];
#pragma unroll
        for (int ni = 0; ni < 4; ni++) {
            const float* bp = &sW[(k0 + tg) * WP + nbase + ni * 8 + g];
            bfr[ni][0] = __float_as_uint(bp[0]);
            bfr[ni][1] = __float_as_uint(bp[4 * WP]);
        }
#pragma unroll
        for (int mi = 0; mi < 4; mi++)
#pragma unroll
            for (int ni = 0; ni < 4; ni++)
                mma_tf32(acc[mi][ni], afr[mi], bfr[ni]);
    }
}

__device__ __forceinline__ void chunk_sum(
    const float* __restrict__ A0, const float* __restrict__ A1, int kof,
    const float* __restrict__ sW, int rbase, int nbase, int g, int tg,
    float acc[4][4][4])
{
#pragma unroll
    for (int ks = 0; ks < 4; ks++) {
        int k0 = ks * 8;
        uint32_t afr[4][4];
#pragma unroll
        for (int mi = 0; mi < 4; mi++) {
            int off = (rbase + mi * 16 + g) * SP + kof + k0 + tg;
            afr[mi][0] = f2tf(A0[off]            + A1[off]);
            afr[mi][1] = f2tf(A0[off + 8 * SP]   + A1[off + 8 * SP]);
            afr[mi][2] = f2tf(A0[off + 4]        + A1[off + 4]);
            afr[mi][3] = f2tf(A0[off + 8*SP + 4] + A1[off + 8*SP + 4]);
        }
        uint32_t bfr[4][2];
#pragma unroll
        for (int ni = 0; ni < 4; ni++) {
            const float* bp = &sW[(k0 + tg) * WP + nbase + ni * 8 + g];
            bfr[ni][0] = __float_as_uint(bp[0]);
            bfr[ni][1] = __float_as_uint(bp[4 * WP]);
        }
#pragma unroll
        for (int mi = 0; mi < 4; mi++)
#pragma unroll
            for (int ni = 0; ni < 4; ni++)
                mma_tf32(acc[mi][ni], afr[mi], bfr[ni]);
    }
}

__global__ __launch_bounds__(256, 1) void node_post_kernel(
    const float* __restrict__ anchor_edge,
    const float* __restrict__ cd1_w, const float* __restrict__ cd1_b,
    const float* __restrict__ cd2_w, const float* __restrict__ cd2_b,
    const float* __restrict__ int_w, const float* __restrict__ int_b,
    float* __restrict__ out_final)
{
    extern __shared__ float smem[];
    float* sPX = smem;                  // [128][SP] tf32(px)
    float* sAG = sPX + TMR * SP;        // [128][SP] tf32(agg)
    float* sH  = sAG + TMR * SP;        // [128][SP] tf32(h), later final-partial
    float* sW  = sH  + TMR * SP;        // [32][WP] weights; also staging scratch

    int tid = threadIdx.x;
    int row0 = blockIdx.x * TMR;

    // stage bsum rows (8-stride) + anchor_edge into sW scratch
    for (int i = tid; i < TMR * 8; i += 256) {
        int n = row0 + (i >> 3);
        sW[i] = (n < N_NODES) ? g_bsum[(size_t)n * 8 + (i & 7)] : 0.f;
    }
    for (int i = tid; i < A_DIM * D_DIM; i += 256) sW[TMR * 8 + i] = anchor_edge[i];
    __syncthreads();

    for (int idx = tid; idx < TMR * D_DIM; idx += 256) {
        int r = idx >> 7, c = idx & 127;
        int n = row0 + r;
        float px = (n < N_NODES) ? g_node_px[(size_t)n * D_DIM + c] : 0.f;
        float ag = 0.f;
#pragma unroll
        for (int a = 0; a < A_DIM; a++)
            ag = fmaf(sW[r * 8 + a], sW[TMR * 8 + a * D_DIM + c], ag);
        sPX[r * SP + c] = __uint_as_float(f2tf(px));
        sAG[r * SP + c] = __uint_as_float(f2tf(ag));
    }

    int lane = tid & 31, wid = tid >> 5;
    int wm = wid >> 2, wn = wid & 3;
    int g = lane >> 2, tg = lane & 3;
    int rbase = wm * 64;
    int nbase = wn * 32;

    float4 wreg[4];
    w_preload(cd1_w, 0, tid, wreg);

    // ---- GEMM1: [px|agg] @ cd1_w, K=256 ----
    float acc1[4][4][4];
#pragma unroll
    for (int mi = 0; mi < 4; mi++)
#pragma unroll
        for (int ni = 0; ni < 4; ni++)
#pragma unroll
            for (int q = 0; q < 4; q++) acc1[mi][ni][q] = 0.f;

    for (int c = 0; c < 8; c++) {
        __syncthreads();
        w_commit(sW, tid, wreg);
        __syncthreads();
        if (c < 7) w_preload(cd1_w, (c + 1) * 32, tid, wreg);
        else       w_preload(int_w, 0, tid, wreg);
        const float* Ab = (c < 4) ? sPX : sAG;
        chunk_pt(Ab, (c & 3) * 32, sW, rbase, nbase, g, tg, acc1);
    }

    // h = tf32(relu(acc1 + b1)) -> sH
#pragma unroll
    for (int mi = 0; mi < 4; mi++)
#pragma unroll
        for (int ni = 0; ni < 4; ni++) {
            int r0 = rbase + mi * 16 + g;
            int c0 = nbase + ni * 8 + 2 * tg;
            float b0v = cd1_b[c0], b1v = cd1_b[c0 + 1];
            sH[r0 * SP + c0]           = __uint_as_float(f2tf(fmaxf(acc1[mi][ni][0] + b0v, 0.f)));
            sH[r0 * SP + c0 + 1]       = __uint_as_float(f2tf(fmaxf(acc1[mi][ni][1] + b1v, 0.f)));
            sH[(r0 + 8) * SP + c0]     = __uint_as_float(f2tf(fmaxf(acc1[mi][ni][2] + b0v, 0.f)));
            sH[(r0 + 8) * SP + c0 + 1] = __uint_as_float(f2tf(fmaxf(acc1[mi][ni][3] + b1v, 0.f)));
        }

    // ---- GEMM3: (px+agg) @ int_w, K=128 ----
    float acc3[4][4][4];
#pragma unroll
    for (int mi = 0; mi < 4; mi++)
#pragma unroll
        for (int ni = 0; ni < 4; ni++)
#pragma unroll
            for (int q = 0; q < 4; q++) acc3[mi][ni][q] = 0.f;

    for (int c = 0; c < 4; c++) {
        __syncthreads();
        w_commit(sW, tid, wreg);
        __syncthreads();
        if (c < 3) w_preload(int_w, (c + 1) * 32, tid, wreg);
        else       w_preload(cd2_w, 0, tid, wreg);
        chunk_sum(sPX, sAG, c * 32, sW, rbase, nbase, g, tg, acc3);
    }

    // ---- GEMM2: h @ cd2_w, K=128 ----
    float acc2[4][4][4];
#pragma unroll
    for (int mi = 0; mi < 4; mi++)
#pragma unroll
        for (int ni = 0; ni < 4; ni++)
#pragma unroll
            for (int q = 0; q < 4; q++) acc2[mi][ni][q] = 0.f;

    for (int c = 0; c < 4; c++) {
        __syncthreads();
        w_commit(sW, tid, wreg);
        __syncthreads();
        if (c < 3) w_preload(cd2_w, (c + 1) * 32, tid, wreg);
        chunk_pt(sH, c * 32, sW, rbase, nbase, g, tg, acc2);
    }
    __syncthreads();   // all sH (h) reads done; safe to overwrite

    // final-partial = sigmoid(acc2+b2) * (acc3+int_b)  -> sH
#pragma unroll
    for (int mi = 0; mi < 4; mi++)
#pragma unroll
        for (int ni = 0; ni < 4; ni++) {
            int r0 = rbase + mi * 16 + g;
            int c0 = nbase + ni * 8 + 2 * tg;
            float bc0 = cd2_b[c0], bc1 = cd2_b[c0 + 1];
            float bi0 = int_b[c0], bi1 = int_b[c0 + 1];
#pragma unroll
            for (int h = 0; h < 2; h++) {
                int rr = r0 + h * 8;
                float cs0 = 1.0f / (1.0f + __expf(-(acc2[mi][ni][2*h]   + bc0)));
                float cs1 = 1.0f / (1.0f + __expf(-(acc2[mi][ni][2*h+1] + bc1)));
                sH[rr * SP + c0]     = cs0 * (acc3[mi][ni][2*h]   + bi0);
                sH[rr * SP + c0 + 1] = cs1 * (acc3[mi][ni][2*h+1] + bi1);
            }
        }
    __syncthreads();

    // out = exact px (global) + final-partial, coalesced float4
    for (int idx = tid; idx < TMR * 32; idx += 256) {
        int r = idx >> 5, c4 = (idx & 31) << 2;
        int n = row0 + r;
        if (n < N_NODES) {
            float4 px4 = *reinterpret_cast<const float4*>(&g_node_px[(size_t)n * D_DIM + c4]);
            const float* hp = &sH[r * SP + c4];
            float4 o = {px4.x + hp[0], px4.y + hp[1], px4.z + hp[2], px4.w + hp[3]};
            *reinterpret_cast<float4*>(&out_final[(size_t)n * D_DIM + c4]) = o;
        }
    }
}

// ---------------------------------------------------------------------------
extern "C" void kernel_launch(void* const* d_in, const int* in_sizes, int n_in,
                              void* d_out, int out_size)
{
    const float* x           = (const float*)d_in[0];
    const float* anchor_node = (const float*)d_in[1];
    const float* attn_w      = (const float*)d_in[2];
    const float* attn_b      = (const float*)d_in[3];
    const float* anchor_edge = (const float*)d_in[4];
    const float* w_w         = (const float*)d_in[5];
    const float* w_b         = (const float*)d_in[6];
    const float* cd1_w       = (const float*)d_in[7];
    const float* cd1_b       = (const float*)d_in[8];
    const float* cd2_w       = (const float*)d_in[9];
    const float* cd2_b       = (const float*)d_in[10];
    const float* int_w       = (const float*)d_in[11];
    const float* int_b       = (const float*)d_in[12];
    const int*   edge_index  = (const int*)d_in[13];
    float* outp = (float*)d_out;   // [0, N*D) = final_x, [N*D, ...) = edge_prompt

    node_pre_kernel<<<(N_NODES + 31) / 32, 256>>>(x, anchor_node, attn_w, attn_b, w_w);
    edge_kernel<<<E_EDGES / 256, 256>>>(edge_index, anchor_edge, w_b,
                                        outp + (size_t)N_NODES * D_DIM);
    cudaFuncSetAttribute(node_post_kernel,
                         cudaFuncAttributeMaxDynamicSharedMemorySize, SMEM_BYTES);
    node_post_kernel<<<(N_NODES + TMR - 1) / TMR, 256, SMEM_BYTES>>>(
        anchor_edge, cd1_w, cd1_b, cd2_w, cd2_b, int_w, int_b, outp);
}

// round 5
// speedup vs baseline: 3.1707x; 1.1251x over previous
#include <cuda_runtime.h>
#include <math.h>
#include <stdint.h>

#define N_NODES 50000
#define E_EDGES 800000
#define D_DIM   128
#define A_DIM   5

// Scratch (no allocations allowed in kernel_launch)
__device__ float g_node_px[N_NODES * D_DIM];       // node_px [N,128]
__device__ float g_s[N_NODES * 16];                // s_src[5] @0, s_dst[5] @8
__device__ float g_bsum[(N_NODES + 128) * 8];      // padded: b-sum per node, 8-stride

__device__ __forceinline__ uint32_t f2tf(float f) {
    uint32_t r; asm("cvt.rna.tf32.f32 %0, %1;" : "=r"(r) : "f"(f)); return r;
}

__device__ __forceinline__ void mma_tf32(float* d, const uint32_t* a, const uint32_t* b) {
    asm volatile("mma.sync.aligned.m16n8k8.row.col.f32.tf32.tf32.f32 "
        "{%0,%1,%2,%3}, {%4,%5,%6,%7}, {%8,%9}, {%0,%1,%2,%3};"
        : "+f"(d[0]), "+f"(d[1]), "+f"(d[2]), "+f"(d[3])
        : "r"(a[0]), "r"(a[1]), "r"(a[2]), "r"(a[3]), "r"(b[0]), "r"(b[1]));
}

// ---------------------------------------------------------------------------
// Kernel 1: per-node precompute, THREAD-per-node.
// All weight reads are warp-uniform smem addresses -> pure broadcast LDS
// (conflict-free). No shuffles. x processed in 4 chunks of 32 floats.
// ---------------------------------------------------------------------------
__global__ __launch_bounds__(256) void node_pre_kernel(
    const float* __restrict__ x,
    const float* __restrict__ anchor_node,
    const float* __restrict__ attn_w,
    const float* __restrict__ attn_b,
    const float* __restrict__ w_w)
{
    __shared__ float shT[20 * D_DIM];   // attnT | wsT | wdT | anchor (each [5][128])
    __shared__ float sh_ab[8];

    int tid = threadIdx.x;
    for (int i = tid; i < 640; i += 256) {
        int a = i >> 7, d = i & 127;
        shT[a * 128 + d]        = attn_w[d * A_DIM + a];
        shT[640 + a * 128 + d]  = w_w[d * A_DIM + a];
        shT[1280 + a * 128 + d] = w_w[(128 + d) * A_DIM + a];
        shT[1920 + i]           = anchor_node[i];
    }
    if (tid < A_DIM) sh_ab[tid] = attn_b[tid];
    __syncthreads();

    int n = blockIdx.x * 256 + tid;
    if (n >= N_NODES) return;

    const float* xrow = x + (size_t)n * D_DIM;

    float aA[A_DIM], aS[A_DIM], aD[A_DIM];
#pragma unroll
    for (int c = 0; c < A_DIM; c++) { aA[c] = 0.f; aS[c] = 0.f; aD[c] = 0.f; }

#pragma unroll 1
    for (int ch = 0; ch < 4; ch++) {
        int base = ch * 32;
        float4 xv[8];
#pragma unroll
        for (int j = 0; j < 8; j++)
            xv[j] = __ldg(reinterpret_cast<const float4*>(xrow + base + 4 * j));
#pragma unroll
        for (int j = 0; j < 8; j++) {
            int col = base + 4 * j;
#pragma unroll
            for (int c = 0; c < A_DIM; c++) {
                float4 wa = *reinterpret_cast<const float4*>(&shT[c * 128 + col]);
                float4 ws = *reinterpret_cast<const float4*>(&shT[640 + c * 128 + col]);
                float4 wd = *reinterpret_cast<const float4*>(&shT[1280 + c * 128 + col]);
                aA[c] = fmaf(xv[j].x, wa.x, fmaf(xv[j].y, wa.y, fmaf(xv[j].z, wa.z, fmaf(xv[j].w, wa.w, aA[c]))));
                aS[c] = fmaf(xv[j].x, ws.x, fmaf(xv[j].y, ws.y, fmaf(xv[j].z, ws.z, fmaf(xv[j].w, ws.w, aS[c]))));
                aD[c] = fmaf(xv[j].x, wd.x, fmaf(xv[j].y, wd.y, fmaf(xv[j].z, wd.z, fmaf(xv[j].w, wd.w, aD[c]))));
            }
        }
    }

    // softmax over 5 attention logits
    float wgt[A_DIM];
    float m = -1e30f;
#pragma unroll
    for (int c = 0; c < A_DIM; c++) { wgt[c] = aA[c] + sh_ab[c]; m = fmaxf(m, wgt[c]); }
    float ssum = 0.f;
#pragma unroll
    for (int c = 0; c < A_DIM; c++) { wgt[c] = __expf(wgt[c] - m); ssum += wgt[c]; }
    float inv = 1.0f / ssum;
#pragma unroll
    for (int c = 0; c < A_DIM; c++) wgt[c] *= inv;

    // node_px = x + w @ anchor (x re-read: L1 hit)
    float* orow = g_node_px + (size_t)n * D_DIM;
#pragma unroll 1
    for (int ch = 0; ch < 4; ch++) {
        int base = ch * 32;
#pragma unroll
        for (int j = 0; j < 8; j++) {
            int col = base + 4 * j;
            float4 o = __ldg(reinterpret_cast<const float4*>(xrow + col));
#pragma unroll
            for (int c = 0; c < A_DIM; c++) {
                float4 an = *reinterpret_cast<const float4*>(&shT[1920 + c * 128 + col]);
                o.x = fmaf(wgt[c], an.x, o.x);
                o.y = fmaf(wgt[c], an.y, o.y);
                o.z = fmaf(wgt[c], an.z, o.z);
                o.w = fmaf(wgt[c], an.w, o.w);
            }
            *reinterpret_cast<float4*>(orow + col) = o;
        }
    }

    float4 sv = {aS[0], aS[1], aS[2], aS[3]};
    float4 dv = {aD[0], aD[1], aD[2], aD[3]};
    *reinterpret_cast<float4*>(&g_s[n * 16])     = sv;
    g_s[n * 16 + 4]                              = aS[4];
    *reinterpret_cast<float4*>(&g_s[n * 16 + 8]) = dv;
    g_s[n * 16 + 12]                             = aD[4];
    float4 z = {0.f, 0.f, 0.f, 0.f};
    *reinterpret_cast<float4*>(&g_bsum[(size_t)n * 8])     = z;
    *reinterpret_cast<float4*>(&g_bsum[(size_t)n * 8 + 4]) = z;
}

// ---------------------------------------------------------------------------
// Kernel 2: edges. Thread-per-edge softmax + vector reds (v4 + scalar per
// endpoint). Warp-per-edge coalesced streaming store of edge_prompt; b via
// shuffle broadcast; anchor_edge in registers.
// ---------------------------------------------------------------------------
__global__ __launch_bounds__(256) void edge_kernel(
    const int* __restrict__ edge_index,
    const float* __restrict__ anchor_edge,
    const float* __restrict__ w_b,
    float* __restrict__ out_edge)
{
    int tid  = threadIdx.x;
    int lane = tid & 31;
    int wid  = tid >> 5;

    float4 ae[A_DIM];
    float  wb[A_DIM];
#pragma unroll
    for (int c = 0; c < A_DIM; c++) {
        ae[c] = __ldg(&reinterpret_cast<const float4*>(anchor_edge + c * D_DIM)[lane]);
        wb[c] = __ldg(&w_b[c]);
    }

    int e = blockIdx.x * 256 + tid;
    int src = edge_index[e];
    int dst = edge_index[E_EDGES + e];

    float4 s03 = *reinterpret_cast<const float4*>(&g_s[src * 16]);
    float  s4  = g_s[src * 16 + 4];
    float4 d03 = *reinterpret_cast<const float4*>(&g_s[dst * 16 + 8]);
    float  d4  = g_s[dst * 16 + 12];

    float b[A_DIM];
    b[0] = s03.x + d03.x + wb[0];
    b[1] = s03.y + d03.y + wb[1];
    b[2] = s03.z + d03.z + wb[2];
    b[3] = s03.w + d03.w + wb[3];
    b[4] = s4    + d4    + wb[4];

    float m = -1e30f;
#pragma unroll
    for (int c = 0; c < A_DIM; c++) {
        b[c] = (b[c] > 0.f) ? b[c] : 0.01f * b[c];   // leaky_relu
        m = fmaxf(m, b[c]);
    }
    float ssum = 0.f;
#pragma unroll
    for (int c = 0; c < A_DIM; c++) { b[c] = __expf(b[c] - m); ssum += b[c]; }
    float inv = 1.0f / ssum;
#pragma unroll
    for (int c = 0; c < A_DIM; c++) b[c] *= inv;

    {
        float* ps = &g_bsum[(size_t)src * 8];
        float* pd = &g_bsum[(size_t)dst * 8];
        asm volatile("red.global.add.v4.f32 [%0], {%1,%2,%3,%4};"
                     :: "l"(ps), "f"(b[0]), "f"(b[1]), "f"(b[2]), "f"(b[3]) : "memory");
        asm volatile("red.global.add.f32 [%0+16], %1;"
                     :: "l"(ps), "f"(b[4]) : "memory");
        asm volatile("red.global.add.v4.f32 [%0], {%1,%2,%3,%4};"
                     :: "l"(pd), "f"(b[0]), "f"(b[1]), "f"(b[2]), "f"(b[3]) : "memory");
        asm volatile("red.global.add.f32 [%0+16], %1;"
                     :: "l"(pd), "f"(b[4]) : "memory");
    }

    size_t ebase = (size_t)blockIdx.x * 256 + wid * 32;
#pragma unroll 4
    for (int le = 0; le < 32; le++) {
        float b0 = __shfl_sync(0xffffffffu, b[0], le);
        float b1 = __shfl_sync(0xffffffffu, b[1], le);
        float b2 = __shfl_sync(0xffffffffu, b[2], le);
        float b3 = __shfl_sync(0xffffffffu, b[3], le);
        float b4 = __shfl_sync(0xffffffffu, b[4], le);
        float4 o;
        o.x = fmaf(b0,ae[0].x, fmaf(b1,ae[1].x, fmaf(b2,ae[2].x, fmaf(b3,ae[3].x, b4*ae[4].x))));
        o.y = fmaf(b0,ae[0].y, fmaf(b1,ae[1].y, fmaf(b2,ae[2].y, fmaf(b3,ae[3].y, b4*ae[4].y))));
        o.z = fmaf(b0,ae[0].z, fmaf(b1,ae[1].z, fmaf(b2,ae[2].z, fmaf(b3,ae[3].z, b4*ae[4].z))));
        o.w = fmaf(b0,ae[0].w, fmaf(b1,ae[1].w, fmaf(b2,ae[2].w, fmaf(b3,ae[3].w, b4*ae[4].w))));
        __stcs(&reinterpret_cast<float4*>(out_edge + (ebase + le) * D_DIM)[lane], o);
    }
}

// ---------------------------------------------------------------------------
// Kernel 3: fused node-side GEMMs (mma tf32), 128x128 per block, register
// double-buffered weight chunks.
// ---------------------------------------------------------------------------
#define TMR 128
#define SP  132
#define WP  136
#define SMEM_FLOATS (3 * TMR * SP + 32 * WP)
#define SMEM_BYTES  (SMEM_FLOATS * 4)

__device__ __forceinline__ void w_preload(const float* __restrict__ W, int kb,
                                          int tid, float4 w[4]) {
#pragma unroll
    for (int j = 0; j < 4; j++) {
        int i = tid + j * 256;
        int r = i >> 5, c4 = (i & 31) << 2;
        w[j] = *reinterpret_cast<const float4*>(&W[(kb + r) * 128 + c4]);
    }
}

__device__ __forceinline__ void w_commit(float* __restrict__ sW, int tid,
                                         const float4 w[4]) {
#pragma unroll
    for (int j = 0; j < 4; j++) {
        int i = tid + j * 256;
        int r = i >> 5, c4 = (i & 31) << 2;
        float* d = &sW[r * WP + c4];
        d[0] = __uint_as_float(f2tf(w[j].x));
        d[1] = __uint_as_float(f2tf(w[j].y));
        d[2] = __uint_as_float(f2tf(w[j].z));
        d[3] = __uint_as_float(f2tf(w[j].w));
    }
}

__device__ __forceinline__ void ldA_pt(const float* __restrict__ A, int row, int kcol,
                                       uint32_t afr[4]) {
    const float* ap = &A[row * SP + kcol];
    afr[0] = __float_as_uint(ap[0]);
    afr[1] = __float_as_uint(ap[8 * SP]);
    afr[2] = __float_as_uint(ap[4]);
    afr[3] = __float_as_uint(ap[8 * SP + 4]);
}

__device__ __forceinline__ void chunk_pt(
    const float* __restrict__ A, int kof, const float* __restrict__ sW,
    int rbase, int nbase, int g, int tg, float acc[4][4][4])
{
#pragma unroll
    for (int ks = 0; ks < 4; ks++) {
        int k0 = ks * 8;
        uint32_t afr[4][4];
#pragma unroll
        for (int mi = 0; mi < 4; mi++)
            ldA_pt(A, rbase + mi * 16 + g, kof + k0 + tg, afr[mi]);
        uint32_t bfr[4][2];
#pragma unroll
        for (int ni = 0; ni < 4; ni++) {
            const float* bp = &sW[(k0 + tg) * WP + nbase + ni * 8 + g];
            bfr[ni][0] = __float_as_uint(bp[0]);
            bfr[ni][1] = __float_as_uint(bp[4 * WP]);
        }
#pragma unroll
        for (int mi = 0; mi < 4; mi++)
#pragma unroll
            for (int ni = 0; ni < 4; ni++)
                mma_tf32(acc[mi][ni], afr[mi], bfr[ni]);
    }
}

__device__ __forceinline__ void chunk_sum(
    const float* __restrict__ A0, const float* __restrict__ A1, int kof,
    const float* __restrict__ sW, int rbase, int nbase, int g, int tg,
    float acc[4][4][4])
{
#pragma unroll
    for (int ks = 0; ks < 4; ks++) {
        int k0 = ks * 8;
        uint32_t afr[4][4];
#pragma unroll
        for (int mi = 0; mi < 4; mi++) {
            int off = (rbase + mi * 16 + g) * SP + kof + k0 + tg;
            afr[mi][0] = f2tf(A0[off]            + A1[off]);
            afr[mi][1] = f2tf(A0[off + 8 * SP]   + A1[off + 8 * SP]);
            afr[mi][2] = f2tf(A0[off + 4]        + A1[off + 4]);
            afr[mi][3] = f2tf(A0[off + 8*SP + 4] + A1[off + 8*SP + 4]);
        }
        uint32_t bfr[4][2];
#pragma unroll
        for (int ni = 0; ni < 4; ni++) {
            const float* bp = &sW[(k0 + tg) * WP + nbase + ni * 8 + g];
            bfr[ni][0] = __float_as_uint(bp[0]);
            bfr[ni][1] = __float_as_uint(bp[4 * WP]);
        }
#pragma unroll
        for (int mi = 0; mi < 4; mi++)
#pragma unroll
            for (int ni = 0; ni < 4; ni++)
                mma_tf32(acc[mi][ni], afr[mi], bfr[ni]);
    }
}

__global__ __launch_bounds__(256, 1) void node_post_kernel(
    const float* __restrict__ anchor_edge,
    const float* __restrict__ cd1_w, const float* __restrict__ cd1_b,
    const float* __restrict__ cd2_w, const float* __restrict__ cd2_b,
    const float* __restrict__ int_w, const float* __restrict__ int_b,
    float* __restrict__ out_final)
{
    extern __shared__ float smem[];
    float* sPX = smem;                  // [128][SP] tf32(px)
    float* sAG = sPX + TMR * SP;        // [128][SP] tf32(agg)
    float* sH  = sAG + TMR * SP;        // [128][SP] tf32(h), later final-partial
    float* sW  = sH  + TMR * SP;        // [32][WP] weights; also staging scratch

    int tid = threadIdx.x;
    int row0 = blockIdx.x * TMR;

    for (int i = tid; i < TMR * 8; i += 256) {
        int n = row0 + (i >> 3);
        sW[i] = (n < N_NODES) ? g_bsum[(size_t)n * 8 + (i & 7)] : 0.f;
    }
    for (int i = tid; i < A_DIM * D_DIM; i += 256) sW[TMR * 8 + i] = anchor_edge[i];
    __syncthreads();

    for (int idx = tid; idx < TMR * D_DIM; idx += 256) {
        int r = idx >> 7, c = idx & 127;
        int n = row0 + r;
        float px = (n < N_NODES) ? g_node_px[(size_t)n * D_DIM + c] : 0.f;
        float ag = 0.f;
#pragma unroll
        for (int a = 0; a < A_DIM; a++)
            ag = fmaf(sW[r * 8 + a], sW[TMR * 8 + a * D_DIM + c], ag);
        sPX[r * SP + c] = __uint_as_float(f2tf(px));
        sAG[r * SP + c] = __uint_as_float(f2tf(ag));
    }

    int lane = tid & 31, wid = tid >> 5;
    int wm = wid >> 2, wn = wid & 3;
    int g = lane >> 2, tg = lane & 3;
    int rbase = wm * 64;
    int nbase = wn * 32;

    float4 wreg[4];
    w_preload(cd1_w, 0, tid, wreg);

    float acc1[4][4][4];
#pragma unroll
    for (int mi = 0; mi < 4; mi++)
#pragma unroll
        for (int ni = 0; ni < 4; ni++)
#pragma unroll
            for (int q = 0; q < 4; q++) acc1[mi][ni][q] = 0.f;

    for (int c = 0; c < 8; c++) {
        __syncthreads();
        w_commit(sW, tid, wreg);
        __syncthreads();
        if (c < 7) w_preload(cd1_w, (c + 1) * 32, tid, wreg);
        else       w_preload(int_w, 0, tid, wreg);
        const float* Ab = (c < 4) ? sPX : sAG;
        chunk_pt(Ab, (c & 3) * 32, sW, rbase, nbase, g, tg, acc1);
    }

#pragma unroll
    for (int mi = 0; mi < 4; mi++)
#pragma unroll
        for (int ni = 0; ni < 4; ni++) {
            int r0 = rbase + mi * 16 + g;
            int c0 = nbase + ni * 8 + 2 * tg;
            float b0v = cd1_b[c0], b1v = cd1_b[c0 + 1];
            sH[r0 * SP + c0]           = __uint_as_float(f2tf(fmaxf(acc1[mi][ni][0] + b0v, 0.f)));
            sH[r0 * SP + c0 + 1]       = __uint_as_float(f2tf(fmaxf(acc1[mi][ni][1] + b1v, 0.f)));
            sH[(r0 + 8) * SP + c0]     = __uint_as_float(f2tf(fmaxf(acc1[mi][ni][2] + b0v, 0.f)));
            sH[(r0 + 8) * SP + c0 + 1] = __uint_as_float(f2tf(fmaxf(acc1[mi][ni][3] + b1v, 0.f)));
        }

    float acc3[4][4][4];
#pragma unroll
    for (int mi = 0; mi < 4; mi++)
#pragma unroll
        for (int ni = 0; ni < 4; ni++)
#pragma unroll
            for (int q = 0; q < 4; q++) acc3[mi][ni][q] = 0.f;

    for (int c = 0; c < 4; c++) {
        __syncthreads();
        w_commit(sW, tid, wreg);
        __syncthreads();
        if (c < 3) w_preload(int_w, (c + 1) * 32, tid, wreg);
        else       w_preload(cd2_w, 0, tid, wreg);
        chunk_sum(sPX, sAG, c * 32, sW, rbase, nbase, g, tg, acc3);
    }

    float acc2[4][4][4];
#pragma unroll
    for (int mi = 0; mi < 4; mi++)
#pragma unroll
        for (int ni = 0; ni < 4; ni++)
#pragma unroll
            for (int q = 0; q < 4; q++) acc2[mi][ni][q] = 0.f;

    for (int c = 0; c < 4; c++) {
        __syncthreads();
        w_commit(sW, tid, wreg);
        __syncthreads();
        if (c < 3) w_preload(cd2_w, (c + 1) * 32, tid, wreg);
        chunk_pt(sH, c * 32, sW, rbase, nbase, g, tg, acc2);
    }
    __syncthreads();

#pragma unroll
    for (int mi = 0; mi < 4; mi++)
#pragma unroll
        for (int ni = 0; ni < 4; ni++) {
            int r0 = rbase + mi * 16 + g;
            int c0 = nbase + ni * 8 + 2 * tg;
            float bc0 = cd2_b[c0], bc1 = cd2_b[c0 + 1];
            float bi0 = int_b[c0], bi1 = int_b[c0 + 1];
#pragma unroll
            for (int h = 0; h < 2; h++) {
                int rr = r0 + h * 8;
                float cs0 = 1.0f / (1.0f + __expf(-(acc2[mi][ni][2*h]   + bc0)));
                float cs1 = 1.0f / (1.0f + __expf(-(acc2[mi][ni][2*h+1] + bc1)));
                sH[rr * SP + c0]     = cs0 * (acc3[mi][ni][2*h]   + bi0);
                sH[rr * SP + c0 + 1] = cs1 * (acc3[mi][ni][2*h+1] + bi1);
            }
        }
    __syncthreads();

    for (int idx = tid; idx < TMR * 32; idx += 256) {
        int r = idx >> 5, c4 = (idx & 31) << 2;
        int n = row0 + r;
        if (n < N_NODES) {
            float4 px4 = *reinterpret_cast<const float4*>(&g_node_px[(size_t)n * D_DIM + c4]);
            const float* hp = &sH[r * SP + c4];
            float4 o = {px4.x + hp[0], px4.y + hp[1], px4.z + hp[2], px4.w + hp[3]};
            *reinterpret_cast<float4*>(&out_final[(size_t)n * D_DIM + c4]) = o;
        }
    }
}

// ---------------------------------------------------------------------------
extern "C" void kernel_launch(void* const* d_in, const int* in_sizes, int n_in,
                              void* d_out, int out_size)
{
    const float* x           = (const float*)d_in[0];
    const float* anchor_node = (const float*)d_in[1];
    const float* attn_w      = (const float*)d_in[2];
    const float* attn_b      = (const float*)d_in[3];
    const float* anchor_edge = (const float*)d_in[4];
    const float* w_w         = (const float*)d_in[5];
    const float* w_b         = (const float*)d_in[6];
    const float* cd1_w       = (const float*)d_in[7];
    const float* cd1_b       = (const float*)d_in[8];
    const float* cd2_w       = (const float*)d_in[9];
    const float* cd2_b       = (const float*)d_in[10];
    const float* int_w       = (const float*)d_in[11];
    const float* int_b       = (const float*)d_in[12];
    const int*   edge_index  = (const int*)d_in[13];
    float* outp = (float*)d_out;   // [0, N*D) = final_x, [N*D, ...) = edge_prompt

    node_pre_kernel<<<(N_NODES + 255) / 256, 256>>>(x, anchor_node, attn_w, attn_b, w_w);
    edge_kernel<<<E_EDGES / 256, 256>>>(edge_index, anchor_edge, w_b,
                                        outp + (size_t)N_NODES * D_DIM);
    cudaFuncSetAttribute(node_post_kernel,
                         cudaFuncAttributeMaxDynamicSharedMemorySize, SMEM_BYTES);
    node_post_kernel<<<(N_NODES + TMR - 1) / TMR, 256, SMEM_BYTES>>>(
        anchor_edge, cd1_w, cd1_b, cd2_w, cd2_b, int_w, int_b, outp);
}

// round 7
// speedup vs baseline: 3.1805x; 1.0031x over previous
#include <cuda_runtime.h>
#include <math.h>
#include <stdint.h>

#define N_NODES 50000
#define E_EDGES 800000
#define D_DIM   128
#define A_DIM   5

// Scratch (no allocations allowed in kernel_launch)
__device__ float g_node_px[N_NODES * D_DIM];       // node_px [N,128]
__device__ float g_s[N_NODES * 16];                // s_src[5] @0, s_dst[5] @8
__device__ float g_bsum[(N_NODES + 128) * 8];      // padded: b-sum per node, 8-stride

__device__ __forceinline__ uint32_t f2tf(float f) {
    uint32_t r; asm("cvt.rna.tf32.f32 %0, %1;" : "=r"(r) : "f"(f)); return r;
}

__device__ __forceinline__ void mma_tf32(float* d, const uint32_t* a, const uint32_t* b) {
    asm volatile("mma.sync.aligned.m16n8k8.row.col.f32.tf32.tf32.f32 "
        "{%0,%1,%2,%3}, {%4,%5,%6,%7}, {%8,%9}, {%0,%1,%2,%3};"
        : "+f"(d[0]), "+f"(d[1]), "+f"(d[2]), "+f"(d[3])
        : "r"(a[0]), "r"(a[1]), "r"(a[2]), "r"(a[3]), "r"(b[0]), "r"(b[1]));
}

// ---------------------------------------------------------------------------
// Kernel 1: per-node precompute, thread-per-node with SMEM-STAGED x tiles.
// Global traffic is fully coalesced; smem access conflict-free via pitch 33.
// ---------------------------------------------------------------------------
#define XP 33                      // x-tile pitch: (row*33+col)%32=(row+col)%32
#define PRE_SMEM_FLOATS (2560 + 8 + 4 * 256 * XP)
#define PRE_SMEM_BYTES  (PRE_SMEM_FLOATS * 4)

__global__ __launch_bounds__(256) void node_pre_kernel(
    const float* __restrict__ x,
    const float* __restrict__ anchor_node,
    const float* __restrict__ attn_w,
    const float* __restrict__ attn_b,
    const float* __restrict__ w_w)
{
    extern __shared__ float psm[];
    float* shT = psm;              // [20][128]: attnT | wsT | wdT | anchorT
    float* sAB = shT + 2560;       // [8]
    float* sx  = sAB + 8;          // [4][256][XP]

    int tid = threadIdx.x;
    int row0 = blockIdx.x * 256;

    for (int i = tid; i < 640; i += 256) {
        int a = i >> 7, d = i & 127;
        shT[a * 128 + d]        = attn_w[d * A_DIM + a];
        shT[640 + a * 128 + d]  = w_w[d * A_DIM + a];
        shT[1280 + a * 128 + d] = w_w[(128 + d) * A_DIM + a];
        shT[1920 + i]           = anchor_node[i];
    }
    if (tid < A_DIM) sAB[tid] = attn_b[tid];

    // stage x[256 rows][128 cols] in 4 chunks of 32 cols; coalesced LDG,
    // conflict-free scalar STS into pitch-33 tiles
#pragma unroll 1
    for (int ch = 0; ch < 4; ch++) {
        float* xt = sx + ch * (256 * XP);
        for (int idx = tid; idx < 2048; idx += 256) {     // 2048 float4
            int r = idx >> 3, c4 = (idx & 7) << 2;
            int n = row0 + r;
            if (n < N_NODES) {
                float4 v = __ldg(reinterpret_cast<const float4*>(
                    &x[(size_t)n * D_DIM + ch * 32 + c4]));
                float* d = &xt[r * XP + c4];
                d[0] = v.x; d[1] = v.y; d[2] = v.z; d[3] = v.w;
            }
        }
    }
    __syncthreads();

    int n = row0 + tid;
    bool act = (n < N_NODES);

    float aA[A_DIM], aS[A_DIM], aD[A_DIM];
#pragma unroll
    for (int c = 0; c < A_DIM; c++) { aA[c] = 0.f; aS[c] = 0.f; aD[c] = 0.f; }

    if (act) {
#pragma unroll 1
        for (int ch = 0; ch < 4; ch++) {
            const float* xr = sx + ch * (256 * XP) + tid * XP;
#pragma unroll
            for (int j4 = 0; j4 < 8; j4++) {
                int col = ch * 32 + j4 * 4;
                float x0 = xr[j4 * 4], x1 = xr[j4 * 4 + 1];
                float x2 = xr[j4 * 4 + 2], x3 = xr[j4 * 4 + 3];
#pragma unroll
                for (int c = 0; c < A_DIM; c++) {
                    float4 wa = *reinterpret_cast<const float4*>(&shT[c * 128 + col]);
                    float4 ws = *reinterpret_cast<const float4*>(&shT[640 + c * 128 + col]);
                    float4 wd = *reinterpret_cast<const float4*>(&shT[1280 + c * 128 + col]);
                    aA[c] = fmaf(x0, wa.x, fmaf(x1, wa.y, fmaf(x2, wa.z, fmaf(x3, wa.w, aA[c]))));
                    aS[c] = fmaf(x0, ws.x, fmaf(x1, ws.y, fmaf(x2, ws.z, fmaf(x3, ws.w, aS[c]))));
                    aD[c] = fmaf(x0, wd.x, fmaf(x1, wd.y, fmaf(x2, wd.z, fmaf(x3, wd.w, aD[c]))));
                }
            }
        }
    }

    // softmax over 5 attention logits
    float wgt[A_DIM];
    float m = -1e30f;
#pragma unroll
    for (int c = 0; c < A_DIM; c++) { wgt[c] = aA[c] + sAB[c]; m = fmaxf(m, wgt[c]); }
    float ssum = 0.f;
#pragma unroll
    for (int c = 0; c < A_DIM; c++) { wgt[c] = __expf(wgt[c] - m); ssum += wgt[c]; }
    float inv = 1.0f / ssum;
#pragma unroll
    for (int c = 0; c < A_DIM; c++) wgt[c] *= inv;

    // px: overwrite own smem row in place, then coalesced STG per chunk
#pragma unroll 1
    for (int ch = 0; ch < 4; ch++) {
        float* xt = sx + ch * (256 * XP);
        if (act) {
            float* xr = xt + tid * XP;
#pragma unroll
            for (int j4 = 0; j4 < 8; j4++) {
                int col = ch * 32 + j4 * 4;
                float o0 = xr[j4 * 4], o1 = xr[j4 * 4 + 1];
                float o2 = xr[j4 * 4 + 2], o3 = xr[j4 * 4 + 3];
#pragma unroll
                for (int c = 0; c < A_DIM; c++) {
                    float4 an = *reinterpret_cast<const float4*>(&shT[1920 + c * 128 + col]);
                    o0 = fmaf(wgt[c], an.x, o0);
                    o1 = fmaf(wgt[c], an.y, o1);
                    o2 = fmaf(wgt[c], an.z, o2);
                    o3 = fmaf(wgt[c], an.w, o3);
                }
                xr[j4 * 4] = o0; xr[j4 * 4 + 1] = o1;
                xr[j4 * 4 + 2] = o2; xr[j4 * 4 + 3] = o3;
            }
        }
        __syncthreads();
        for (int idx = tid; idx < 2048; idx += 256) {
            int r = idx >> 3, c4 = (idx & 7) << 2;
            int n2 = row0 + r;
            if (n2 < N_NODES) {
                const float* p = &xt[r * XP + c4];
                float4 v = {p[0], p[1], p[2], p[3]};
                *reinterpret_cast<float4*>(
                    &g_node_px[(size_t)n2 * D_DIM + ch * 32 + c4]) = v;
            }
        }
    }

    if (act) {
        float4 sv = {aS[0], aS[1], aS[2], aS[3]};
        float4 dv = {aD[0], aD[1], aD[2], aD[3]};
        *reinterpret_cast<float4*>(&g_s[n * 16])     = sv;
        g_s[n * 16 + 4]                              = aS[4];
        *reinterpret_cast<float4*>(&g_s[n * 16 + 8]) = dv;
        g_s[n * 16 + 12]                             = aD[4];
        float4 z = {0.f, 0.f, 0.f, 0.f};
        *reinterpret_cast<float4*>(&g_bsum[(size_t)n * 8])     = z;
        *reinterpret_cast<float4*>(&g_bsum[(size_t)n * 8 + 4]) = z;
    }
}

// ---------------------------------------------------------------------------
// Kernel 2: edges (unchanged from R5). Thread-per-edge softmax + vector reds;
// warp-per-edge coalesced streaming store; b via shuffle broadcast.
// ---------------------------------------------------------------------------
__global__ __launch_bounds__(256) void edge_kernel(
    const int* __restrict__ edge_index,
    const float* __restrict__ anchor_edge,
    const float* __restrict__ w_b,
    float* __restrict__ out_edge)
{
    int tid  = threadIdx.x;
    int lane = tid & 31;
    int wid  = tid >> 5;

    float4 ae[A_DIM];
    float  wb[A_DIM];
#pragma unroll
    for (int c = 0; c < A_DIM; c++) {
        ae[c] = __ldg(&reinterpret_cast<const float4*>(anchor_edge + c * D_DIM)[lane]);
        wb[c] = __ldg(&w_b[c]);
    }

    int e = blockIdx.x * 256 + tid;
    int src = edge_index[e];
    int dst = edge_index[E_EDGES + e];

    float4 s03 = *reinterpret_cast<const float4*>(&g_s[src * 16]);
    float  s4  = g_s[src * 16 + 4];
    float4 d03 = *reinterpret_cast<const float4*>(&g_s[dst * 16 + 8]);
    float  d4  = g_s[dst * 16 + 12];

    float b[A_DIM];
    b[0] = s03.x + d03.x + wb[0];
    b[1] = s03.y + d03.y + wb[1];
    b[2] = s03.z + d03.z + wb[2];
    b[3] = s03.w + d03.w + wb[3];
    b[4] = s4    + d4    + wb[4];

    float m = -1e30f;
#pragma unroll
    for (int c = 0; c < A_DIM; c++) {
        b[c] = (b[c] > 0.f) ? b[c] : 0.01f * b[c];   // leaky_relu
        m = fmaxf(m, b[c]);
    }
    float ssum = 0.f;
#pragma unroll
    for (int c = 0; c < A_DIM; c++) { b[c] = __expf(b[c] - m); ssum += b[c]; }
    float inv = 1.0f / ssum;
#pragma unroll
    for (int c = 0; c < A_DIM; c++) b[c] *= inv;

    {
        float* ps = &g_bsum[(size_t)src * 8];
        float* pd = &g_bsum[(size_t)dst * 8];
        asm volatile("red.global.add.v4.f32 [%0], {%1,%2,%3,%4};"
                     :: "l"(ps), "f"(b[0]), "f"(b[1]), "f"(b[2]), "f"(b[3]) : "memory");
        asm volatile("red.global.add.f32 [%0+16], %1;"
                     :: "l"(ps), "f"(b[4]) : "memory");
        asm volatile("red.global.add.v4.f32 [%0], {%1,%2,%3,%4};"
                     :: "l"(pd), "f"(b[0]), "f"(b[1]), "f"(b[2]), "f"(b[3]) : "memory");
        asm volatile("red.global.add.f32 [%0+16], %1;"
                     :: "l"(pd), "f"(b[4]) : "memory");
    }

    size_t ebase = (size_t)blockIdx.x * 256 + wid * 32;
#pragma unroll 4
    for (int le = 0; le < 32; le++) {
        float b0 = __shfl_sync(0xffffffffu, b[0], le);
        float b1 = __shfl_sync(0xffffffffu, b[1], le);
        float b2 = __shfl_sync(0xffffffffu, b[2], le);
        float b3 = __shfl_sync(0xffffffffu, b[3], le);
        float b4 = __shfl_sync(0xffffffffu, b[4], le);
        float4 o;
        o.x = fmaf(b0,ae[0].x, fmaf(b1,ae[1].x, fmaf(b2,ae[2].x, fmaf(b3,ae[3].x, b4*ae[4].x))));
        o.y = fmaf(b0,ae[0].y, fmaf(b1,ae[1].y, fmaf(b2,ae[2].y, fmaf(b3,ae[3].y, b4*ae[4].y))));
        o.z = fmaf(b0,ae[0].z, fmaf(b1,ae[1].z, fmaf(b2,ae[2].z, fmaf(b3,ae[3].z, b4*ae[4].z))));
        o.w = fmaf(b0,ae[0].w, fmaf(b1,ae[1].w, fmaf(b2,ae[2].w, fmaf(b3,ae[3].w, b4*ae[4].w))));
        __stcs(&reinterpret_cast<float4*>(out_edge + (ebase + le) * D_DIM)[lane], o);
    }
}

// ---------------------------------------------------------------------------
// Kernel 3: fused node-side GEMMs (mma tf32), 128x128 per block, register
// double-buffered weight chunks; vectorized STS.128 commit.
// ---------------------------------------------------------------------------
#define TMR 128
#define SP  132
#define WP  136
#define SMEM_FLOATS (3 * TMR * SP + 32 * WP)
#define SMEM_BYTES  (SMEM_FLOATS * 4)

__device__ __forceinline__ void w_preload(const float* __restrict__ W, int kb,
                                          int tid, float4 w[4]) {
#pragma unroll
    for (int j = 0; j < 4; j++) {
        int i = tid + j * 256;
        int r = i >> 5, c4 = (i & 31) << 2;
        w[j] = __ldg(reinterpret_cast<const float4*>(&W[(kb + r) * 128 + c4]));
    }
}

__device__ __forceinline__ void w_commit(float* __restrict__ sW, int tid,
                                         const float4 w[4]) {
#pragma unroll
    for (int j = 0; j < 4; j++) {
        int i = tid + j * 256;
        int r = i >> 5, c4 = (i & 31) << 2;
        float4 t;
        t.x = __uint_as_float(f2tf(w[j].x));
        t.y = __uint_as_float(f2tf(w[j].y));
        t.z = __uint_as_float(f2tf(w[j].z));
        t.w = __uint_as_float(f2tf(w[j].w));
        *reinterpret_cast<float4*>(&sW[r * WP + c4]) = t;   // WP%4==0 -> aligned
    }
}

__device__ __forceinline__ void ldA_pt(const float* __restrict__ A, int row, int kcol,
                                       uint32_t afr[4]) {
    const float* ap = &A[row * SP + kcol];
    afr[0] = __float_as_uint(ap[0]);
    afr[1] = __float_as_uint(ap[8 * SP]);
    afr[2] = __float_as_uint(ap[4]);
    afr[3] = __float_as_uint(ap[8 * SP + 4]);
}

__device__ __forceinline__ void chunk_pt(
    const float* __restrict__ A, int kof, const float* __restrict__ sW,
    int rbase, int nbase, int g, int tg, float acc[4][4][4])
{
#pragma unroll
    for (int ks = 0; ks < 4; ks++) {
        int k0 = ks * 8;
        uint32_t afr[4][4];
#pragma unroll
        for (int mi = 0; mi < 4; mi++)
            ldA_pt(A, rbase + mi * 16 + g, kof + k0 + tg, afr[mi]);
        uint32_t bfr[4][2];
#pragma unroll
        for (int ni = 0; ni < 4; ni++) {
            const float* bp = &sW[(k0 + tg) * WP + nbase + ni * 8 + g];
            bfr[ni][0] = __float_as_uint(bp[0]);
            bfr[ni][1] = __float_as_uint(bp[4 * WP]);
        }
#pragma unroll
        for (int mi = 0; mi < 4; mi++)
#pragma unroll
            for (int ni = 0; ni < 4; ni++)
                mma_tf32(acc[mi][ni], afr[mi], bfr[ni]);
    }
}

__device__ __forceinline__ void chunk_sum(
    const float* __restrict__ A0, const float* __restrict__ A1, int kof,
    const float* __restrict__ sW, int rbase, int nbase, int g, int tg,
    float acc[4][4][4])
{
#pragma unroll
    for (int ks = 0; ks < 4; ks++) {
        int k0 = ks * 8;
        uint32_t afr[4][4];
#pragma unroll
        for (int mi = 0; mi < 4; mi++) {
            int off = (rbase + mi * 16 + g) * SP + kof + k0 + tg;
            afr[mi][0] = f2tf(A0[off]            + A1[off]);
            afr[mi][1] = f2tf(A0[off + 8 * SP]   + A1[off + 8 * SP]);
            afr[mi][2] = f2tf(A0[off + 4]        + A1[off + 4]);
            afr[mi][3] = f2tf(A0[off + 8*SP + 4] + A1[off + 8*SP + 4]);
        }
        uint32_t bfr[4][2];
#pragma unroll
        for (int ni = 0; ni < 4; ni++) {
            const float* bp = &sW[(k0 + tg) * WP + nbase + ni * 8 + g];
            bfr[ni][0] = __float_as_uint(bp[0]);
            bfr[ni][1] = __float_as_uint(bp[4 * WP]);
        }
#pragma unroll
        for (int mi = 0; mi < 4; mi++)
#pragma unroll
            for (int ni = 0; ni < 4; ni++)
                mma_tf32(acc[mi][ni], afr[mi], bfr[ni]);
    }
}

__global__ __launch_bounds__(256, 1) void node_post_kernel(
    const float* __restrict__ anchor_edge,
    const float* __restrict__ cd1_w, const float* __restrict__ cd1_b,
    const float* __restrict__ cd2_w, const float* __restrict__ cd2_b,
    const float* __restrict__ int_w, const float* __restrict__ int_b,
    float* __restrict__ out_final)
{
    extern __shared__ float smem[];
    float* sPX = smem;
    float* sAG = sPX + TMR * SP;
    float* sH  = sAG + TMR * SP;
    float* sW  = sH  + TMR * SP;

    int tid = threadIdx.x;
    int row0 = blockIdx.x * TMR;

    for (int i = tid; i < TMR * 8; i += 256) {
        int n = row0 + (i >> 3);
        sW[i] = (n < N_NODES) ? g_bsum[(size_t)n * 8 + (i & 7)] : 0.f;
    }
    for (int i = tid; i < A_DIM * D_DIM; i += 256) sW[TMR * 8 + i] = anchor_edge[i];
    __syncthreads();

    for (int idx = tid; idx < TMR * D_DIM; idx += 256) {
        int r = idx >> 7, c = idx & 127;
        int n = row0 + r;
        float px = (n < N_NODES) ? g_node_px[(size_t)n * D_DIM + c] : 0.f;
        float ag = 0.f;
#pragma unroll
        for (int a = 0; a < A_DIM; a++)
            ag = fmaf(sW[r * 8 + a], sW[TMR * 8 + a * D_DIM + c], ag);
        sPX[r * SP + c] = __uint_as_float(f2tf(px));
        sAG[r * SP + c] = __uint_as_float(f2tf(ag));
    }

    int lane = tid & 31, wid = tid >> 5;
    int wm = wid >> 2, wn = wid & 3;
    int g = lane >> 2, tg = lane & 3;
    int rbase = wm * 64;
    int nbase = wn * 32;

    float4 wreg[4];
    w_preload(cd1_w, 0, tid, wreg);

    float acc1[4][4][4];
#pragma unroll
    for (int mi = 0; mi < 4; mi++)
#pragma unroll
        for (int ni = 0; ni < 4; ni++)
#pragma unroll
            for (int q = 0; q < 4; q++) acc1[mi][ni][q] = 0.f;

    for (int c = 0; c < 8; c++) {
        __syncthreads();
        w_commit(sW, tid, wreg);
        __syncthreads();
        if (c < 7) w_preload(cd1_w, (c + 1) * 32, tid, wreg);
        else       w_preload(int_w, 0, tid, wreg);
        const float* Ab = (c < 4) ? sPX : sAG;
        chunk_pt(Ab, (c & 3) * 32, sW, rbase, nbase, g, tg, acc1);
    }

#pragma unroll
    for (int mi = 0; mi < 4; mi++)
#pragma unroll
        for (int ni = 0; ni < 4; ni++) {
            int r0 = rbase + mi * 16 + g;
            int c0 = nbase + ni * 8 + 2 * tg;
            float b0v = cd1_b[c0], b1v = cd1_b[c0 + 1];
            sH[r0 * SP + c0]           = __uint_as_float(f2tf(fmaxf(acc1[mi][ni][0] + b0v, 0.f)));
            sH[r0 * SP + c0 + 1]       = __uint_as_float(f2tf(fmaxf(acc1[mi][ni][1] + b1v, 0.f)));
            sH[(r0 + 8) * SP + c0]     = __uint_as_float(f2tf(fmaxf(acc1[mi][ni][2] + b0v, 0.f)));
            sH[(r0 + 8) * SP + c0 + 1] = __uint_as_float(f2tf(fmaxf(acc1[mi][ni][3] + b1v, 0.f)));
        }

    float acc3[4][4][4];
#pragma unroll
    for (int mi = 0; mi < 4; mi++)
#pragma unroll
        for (int ni = 0; ni < 4; ni++)
#pragma unroll
            for (int q = 0; q < 4; q++) acc3[mi][ni][q] = 0.f;

    for (int c = 0; c < 4; c++) {
        __syncthreads();
        w_commit(sW, tid, wreg);
        __syncthreads();
        if (c < 3) w_preload(int_w, (c + 1) * 32, tid, wreg);
        else       w_preload(cd2_w, 0, tid, wreg);
        chunk_sum(sPX, sAG, c * 32, sW, rbase, nbase, g, tg, acc3);
    }

    float acc2[4][4][4];
#pragma unroll
    for (int mi = 0; mi < 4; mi++)
#pragma unroll
        for (int ni = 0; ni < 4; ni++)
#pragma unroll
            for (int q = 0; q < 4; q++) acc2[mi][ni][q] = 0.f;

    for (int c = 0; c < 4; c++) {
        __syncthreads();
        w_commit(sW, tid, wreg);
        __syncthreads();
        if (c < 3) w_preload(cd2_w, (c + 1) * 32, tid, wreg);
        chunk_pt(sH, c * 32, sW, rbase, nbase, g, tg, acc2);
    }
    __syncthreads();

#pragma unroll
    for (int mi = 0; mi < 4; mi++)
#pragma unroll
        for (int ni = 0; ni < 4; ni++) {
            int r0 = rbase + mi * 16 + g;
            int c0 = nbase + ni * 8 + 2 * tg;
            float bc0 = cd2_b[c0], bc1 = cd2_b[c0 + 1];
            float bi0 = int_b[c0], bi1 = int_b[c0 + 1];
#pragma unroll
            for (int h = 0; h < 2; h++) {
                int rr = r0 + h * 8;
                float cs0 = 1.0f / (1.0f + __expf(-(acc2[mi][ni][2*h]   + bc0)));
                float cs1 = 1.0f / (1.0f + __expf(-(acc2[mi][ni][2*h+1] + bc1)));
                sH[rr * SP + c0]     = cs0 * (acc3[mi][ni][2*h]   + bi0);
                sH[rr * SP + c0 + 1] = cs1 * (acc3[mi][ni][2*h+1] + bi1);
            }
        }
    __syncthreads();

    for (int idx = tid; idx < TMR * 32; idx += 256) {
        int r = idx >> 5, c4 = (idx & 31) << 2;
        int n = row0 + r;
        if (n < N_NODES) {
            float4 px4 = *reinterpret_cast<const float4*>(&g_node_px[(size_t)n * D_DIM + c4]);
            const float* hp = &sH[r * SP + c4];
            float4 o = {px4.x + hp[0], px4.y + hp[1], px4.z + hp[2], px4.w + hp[3]};
            *reinterpret_cast<float4*>(&out_final[(size_t)n * D_DIM + c4]) = o;
        }
    }
}

// ---------------------------------------------------------------------------
extern "C" void kernel_launch(void* const* d_in, const int* in_sizes, int n_in,
                              void* d_out, int out_size)
{
    const float* x           = (const float*)d_in[0];
    const float* anchor_node = (const float*)d_in[1];
    const float* attn_w      = (const float*)d_in[2];
    const float* attn_b      = (const float*)d_in[3];
    const float* anchor_edge = (const float*)d_in[4];
    const float* w_w         = (const float*)d_in[5];
    const float* w_b         = (const float*)d_in[6];
    const float* cd1_w       = (const float*)d_in[7];
    const float* cd1_b       = (const float*)d_in[8];
    const float* cd2_w       = (const float*)d_in[9];
    const float* cd2_b       = (const float*)d_in[10];
    const float* int_w       = (const float*)d_in[11];
    const float* int_b       = (const float*)d_in[12];
    const int*   edge_index  = (const int*)d_in[13];
    float* outp = (float*)d_out;   // [0, N*D) = final_x, [N*D, ...) = edge_prompt

    cudaFuncSetAttribute(node_pre_kernel,
                         cudaFuncAttributeMaxDynamicSharedMemorySize, PRE_SMEM_BYTES);
    node_pre_kernel<<<(N_NODES + 255) / 256, 256, PRE_SMEM_BYTES>>>(
        x, anchor_node, attn_w, attn_b, w_w);
    edge_kernel<<<E_EDGES / 256, 256>>>(edge_index, anchor_edge, w_b,
                                        outp + (size_t)N_NODES * D_DIM);
    cudaFuncSetAttribute(node_post_kernel,
                         cudaFuncAttributeMaxDynamicSharedMemorySize, SMEM_BYTES);
    node_post_kernel<<<(N_NODES + TMR - 1) / TMR, 256, SMEM_BYTES>>>(
        anchor_edge, cd1_w, cd1_b, cd2_w, cd2_b, int_w, int_b, outp);
}